// round 12
// baseline (speedup 1.0000x reference)
#include <cuda_runtime.h>
#include <cuda_bf16.h>
#include <math.h>
#include <stdint.h>

// ---------------- problem constants ----------------
#define S_Q      1024
#define D_MODEL  640
#define N_HEADS  8
#define HD       80
#define ENC_LEN  77
#define ENC_DIM  768
#define FF_IN    2560
#define PROJ_N   5120
#define BF_MAX   8
#define ROWS_MAX (BF_MAX * S_Q)
#define ATTN_SCALE 0.11180339887498949f
#define NEG_BIG  -3.0e38f
#define NSM      148
#define PERSIST_BLOCKS (2 * NSM)   // 296

// ---------------- scratch ----------------
__device__ float g_x[ROWS_MAX * D_MODEL];
__device__ float g_qkv[ROWS_MAX * 3 * D_MODEL];
__device__ float g_q2[ROWS_MAX * D_MODEL];
__device__ float g_kv[1024 * 2 * D_MODEL];
__device__ float g_attn[ROWS_MAX * D_MODEL];
__device__ float g_h2[ROWS_MAX * D_MODEL];
__device__ float g_h3[ROWS_MAX * D_MODEL];
__device__ float g_gated[ROWS_MAX * FF_IN];
__device__ float g_wqkv[D_MODEL * 3 * D_MODEL];
__device__ float g_wkv[ENC_DIM * 2 * D_MODEL];
__device__ float g_w1p[D_MODEL * PROJ_N];
__device__ float g_b1p[PROJ_N];

// ---------------- mma / cp.async helpers ----------------
__device__ __forceinline__ float to_tf32(float x) {
    uint32_t r;
    asm("cvt.rna.tf32.f32 %0, %1;" : "=r"(r) : "f"(x));
    return __uint_as_float(r);
}
__device__ __forceinline__ void mma_tf32(float c[4], const uint32_t a[4], const uint32_t b[2]) {
    asm volatile(
        "mma.sync.aligned.m16n8k8.row.col.f32.tf32.tf32.f32 "
        "{%0,%1,%2,%3}, {%4,%5,%6,%7}, {%8,%9}, {%0,%1,%2,%3};"
        : "+f"(c[0]), "+f"(c[1]), "+f"(c[2]), "+f"(c[3])
        : "r"(a[0]), "r"(a[1]), "r"(a[2]), "r"(a[3]), "r"(b[0]), "r"(b[1]));
}
__device__ __forceinline__ void cp16(float* smem, const float* gmem) {
    uint32_t a = (uint32_t)__cvta_generic_to_shared(smem);
    asm volatile("cp.async.cg.shared.global [%0], [%1], 16;" :: "r"(a), "l"(gmem));
}
#define CP_COMMIT() asm volatile("cp.async.commit_group;")
#define CP_WAIT2()  asm volatile("cp.async.wait_group 2;")
#define CP_WAIT0()  asm volatile("cp.async.wait_group 0;")

__device__ __forceinline__ float gelu_tanh(float g) {
    const float u = 0.7978845608028654f * (g + 0.044715f * g * g * g);
    return g * __frcp_rn(1.0f + __expf(-2.0f * u));
}

// ---------------- weight packing ----------------
__global__ void pack3_kernel(const float* __restrict__ a, const float* __restrict__ b,
                             const float* __restrict__ c, float* __restrict__ out,
                             int rows, int cols) {
    const int idx = blockIdx.x * blockDim.x + threadIdx.x;
    if (idx >= rows * cols) return;
    const int r = idx / cols, j = idx - r * cols;
    float* o = out + (size_t)r * 3 * cols;
    o[j] = a[idx]; o[cols + j] = b[idx]; o[2 * cols + j] = c[idx];
}
__global__ void pack2_kernel(const float* __restrict__ a, const float* __restrict__ b,
                             float* __restrict__ out, int rows, int cols) {
    const int idx = blockIdx.x * blockDim.x + threadIdx.x;
    if (idx >= rows * cols) return;
    const int r = idx / cols, j = idx - r * cols;
    float* o = out + (size_t)r * 2 * cols;
    o[j] = a[idx]; o[cols + j] = b[idx];
}
__global__ void packw1_kernel(const float* __restrict__ w, float* __restrict__ out) {
    const int idx = blockIdx.x * blockDim.x + threadIdx.x;
    if (idx >= D_MODEL * PROJ_N) return;
    const int k = idx / PROJ_N, c = idx - k * PROJ_N;
    const int j = c >> 1, s = c & 1;
    out[idx] = w[(size_t)k * PROJ_N + s * FF_IN + j];
}
__global__ void packb1_kernel(const float* __restrict__ b, float* __restrict__ out) {
    const int idx = blockIdx.x * blockDim.x + threadIdx.x;
    if (idx >= PROJ_N) return;
    const int j = idx >> 1, s = idx & 1;
    out[idx] = b[s * FF_IN + j];
}

// ---------------- LayerNorm ----------------
__global__ void ln_kernel(const float* __restrict__ x, const float* __restrict__ w,
                          const float* __restrict__ b, float* __restrict__ out) {
    const int row = blockIdx.x;
    const float* xr = x + (size_t)row * D_MODEL;
    float* orow = out + (size_t)row * D_MODEL;

    float s = 0.f, s2 = 0.f;
    for (int i = threadIdx.x; i < D_MODEL; i += blockDim.x) {
        float v = xr[i];
        s += v; s2 += v * v;
    }
    __shared__ float red[64];
    #pragma unroll
    for (int o = 16; o; o >>= 1) {
        s  += __shfl_xor_sync(0xFFFFFFFFu, s,  o);
        s2 += __shfl_xor_sync(0xFFFFFFFFu, s2, o);
    }
    int wid = threadIdx.x >> 5, nw = blockDim.x >> 5;
    if ((threadIdx.x & 31) == 0) { red[wid] = s; red[32 + wid] = s2; }
    __syncthreads();
    if (threadIdx.x < 32) {
        s  = (threadIdx.x < nw) ? red[threadIdx.x]      : 0.f;
        s2 = (threadIdx.x < nw) ? red[32 + threadIdx.x] : 0.f;
        #pragma unroll
        for (int o = 16; o; o >>= 1) {
            s  += __shfl_xor_sync(0xFFFFFFFFu, s,  o);
            s2 += __shfl_xor_sync(0xFFFFFFFFu, s2, o);
        }
        if (threadIdx.x == 0) { red[0] = s; red[1] = s2; }
    }
    __syncthreads();
    const float mean = red[0] * (1.0f / D_MODEL);
    const float var  = red[1] * (1.0f / D_MODEL) - mean * mean;
    const float rstd = rsqrtf(var + 1e-5f);
    for (int i = threadIdx.x; i < D_MODEL; i += blockDim.x)
        orow[i] = (xr[i] - mean) * rstd * w[i] + b[i];
}

// ---------------- persistent tf32 GEMM: 128x128 tiles, 8 warps, warp 32x64, BK16, 4-stage ----------------
#define ASTR 20
#define BSTR 136
#define GSTAGES 4

template<int GELU_FUSE>
__global__ __launch_bounds__(256, 2) void gemm_tf32_kernel_t(
    const float* __restrict__ A, const float* __restrict__ B,
    const float* __restrict__ bias, const float* __restrict__ resid,
    float* __restrict__ C, int M, int N, int K)
{
    __shared__ float As[GSTAGES][128 * ASTR];
    __shared__ float Bs[GSTAGES][16 * BSTR];

    const int tid  = threadIdx.x;
    const int lane = tid & 31, warp = tid >> 5;
    const int wm = warp & 3, wn = warp >> 2;
    const int g  = lane >> 2, tg = lane & 3;

    const int ar0 = (tid * 2) >> 2, ac0 = ((tid * 2) & 3) * 4;
    const int ar1 = (tid * 2 + 1) >> 2, ac1 = ((tid * 2 + 1) & 3) * 4;
    const int br0 = (tid * 2) >> 5, bc0 = ((tid * 2) & 31) * 4;
    const int br1 = (tid * 2 + 1) >> 5, bc1 = ((tid * 2 + 1) & 31) * 4;

    const int T = K >> 4;
    const int gridN = N >> 7;
    const int nTiles = gridN * ((M + 127) >> 7);

    for (int tile = blockIdx.x; tile < nTiles; tile += gridDim.x) {
        const int bx = tile % gridN, by = tile / gridN;
        const int bm = by * 128, bn = bx * 128;

        const float* Ap0 = A + (size_t)min(bm + ar0, M - 1) * K + ac0;
        const float* Ap1 = A + (size_t)min(bm + ar1, M - 1) * K + ac1;
        const float* Bp0 = B + (size_t)br0 * N + bn + bc0;
        const float* Bp1 = B + (size_t)br1 * N + bn + bc1;

        float acc[2][8][4];
        #pragma unroll
        for (int mt = 0; mt < 2; mt++)
            #pragma unroll
            for (int nt = 0; nt < 8; nt++)
                #pragma unroll
                for (int i = 0; i < 4; i++) acc[mt][nt][i] = 0.f;

        #pragma unroll
        for (int s = 0; s < GSTAGES - 1; s++) {
            if (s < T) {
                cp16(&As[s][ar0 * ASTR + ac0], Ap0 + s * 16);
                cp16(&As[s][ar1 * ASTR + ac1], Ap1 + s * 16);
                cp16(&Bs[s][br0 * BSTR + bc0], Bp0 + (size_t)s * 16 * N);
                cp16(&Bs[s][br1 * BSTR + bc1], Bp1 + (size_t)s * 16 * N);
            }
            CP_COMMIT();
        }

        for (int t = 0; t < T; t++) {
            CP_WAIT2();
            __syncthreads();

            const int cur = t & (GSTAGES - 1);
            const float* as = As[cur];
            const float* bs = Bs[cur];
            #pragma unroll
            for (int k8 = 0; k8 < 2; k8++) {
                uint32_t af[2][4], bf[8][2];
                #pragma unroll
                for (int mt = 0; mt < 2; mt++) {
                    const float* p  = as + (wm * 32 + mt * 16 + g) * ASTR + k8 * 8 + tg;
                    const float* p8 = p + 8 * ASTR;
                    af[mt][0] = __float_as_uint(p[0]);
                    af[mt][1] = __float_as_uint(p8[0]);
                    af[mt][2] = __float_as_uint(p[4]);
                    af[mt][3] = __float_as_uint(p8[4]);
                }
                #pragma unroll
                for (int nt = 0; nt < 8; nt++) {
                    const float* p = bs + (k8 * 8 + tg) * BSTR + wn * 64 + nt * 8 + g;
                    bf[nt][0] = __float_as_uint(p[0]);
                    bf[nt][1] = __float_as_uint(p[4 * BSTR]);
                }
                #pragma unroll
                for (int mt = 0; mt < 2; mt++)
                    #pragma unroll
                    for (int nt = 0; nt < 8; nt++)
                        mma_tf32(acc[mt][nt], af[mt], bf[nt]);
            }

            const int tn = t + GSTAGES - 1;
            if (tn < T) {
                const int nxt = tn & (GSTAGES - 1);
                cp16(&As[nxt][ar0 * ASTR + ac0], Ap0 + tn * 16);
                cp16(&As[nxt][ar1 * ASTR + ac1], Ap1 + tn * 16);
                cp16(&Bs[nxt][br0 * BSTR + bc0], Bp0 + (size_t)tn * 16 * N);
                cp16(&Bs[nxt][br1 * BSTR + bc1], Bp1 + (size_t)tn * 16 * N);
            }
            CP_COMMIT();
        }

        // epilogue
        if (GELU_FUSE) {
            const int NO = N >> 1;
            #pragma unroll
            for (int nt = 0; nt < 8; nt++) {
                const int c = bn + wn * 64 + nt * 8 + tg * 2;
                const float2 bv = *(const float2*)(bias + c);
                const int j = c >> 1;
                #pragma unroll
                for (int mt = 0; mt < 2; mt++) {
                    const int r0 = bm + wm * 32 + mt * 16 + g;
                    if (r0 < M)
                        C[(size_t)r0 * NO + j] = (acc[mt][nt][0] + bv.x) * gelu_tanh(acc[mt][nt][1] + bv.y);
                    const int r1 = r0 + 8;
                    if (r1 < M)
                        C[(size_t)r1 * NO + j] = (acc[mt][nt][2] + bv.x) * gelu_tanh(acc[mt][nt][3] + bv.y);
                }
            }
        } else {
            #pragma unroll
            for (int nt = 0; nt < 8; nt++) {
                const int c = bn + wn * 64 + nt * 8 + tg * 2;
                float bx2 = 0.f, by2 = 0.f;
                if (bias) { const float2 bv = *(const float2*)(bias + c); bx2 = bv.x; by2 = bv.y; }
                #pragma unroll
                for (int mt = 0; mt < 2; mt++) {
                    const int r0 = bm + wm * 32 + mt * 16 + g;
                    if (r0 < M) {
                        float2 v = make_float2(acc[mt][nt][0] + bx2, acc[mt][nt][1] + by2);
                        if (resid) { const float2 rv = *(const float2*)(resid + (size_t)r0 * N + c); v.x += rv.x; v.y += rv.y; }
                        *(float2*)(C + (size_t)r0 * N + c) = v;
                    }
                    const int r1 = r0 + 8;
                    if (r1 < M) {
                        float2 v = make_float2(acc[mt][nt][2] + bx2, acc[mt][nt][3] + by2);
                        if (resid) { const float2 rv = *(const float2*)(resid + (size_t)r1 * N + c); v.x += rv.x; v.y += rv.y; }
                        *(float2*)(C + (size_t)r1 * N + c) = v;
                    }
                }
            }
        }

        // drain outstanding cp.async groups and guard smem reuse across tiles
        CP_WAIT0();
        __syncthreads();
    }
}

// ---------------- tf32 MMA flash attention: 128-query tile, 8 warps (R9-proven) ----------------
#define QSTR 84
#define KSTR 72
#define VSTR 88
#define PSTR 76
#define QS_OFF 0
#define KS_OFF (128 * QSTR)
#define VS_OFF (KS_OFF + 80 * KSTR)
#define PS_OFF (VS_OFF + 64 * VSTR)
#define ATTN_SMEM_FLOATS (PS_OFF + 128 * PSTR)
#define ATTN_SMEM_BYTES  (ATTN_SMEM_FLOATS * 4)

__global__ __launch_bounds__(256, 1) void attn_mma_kernel(
    const float* __restrict__ Q, const float* __restrict__ Kbuf,
    const float* __restrict__ Vbuf, float* __restrict__ O,
    const int* __restrict__ vlp, int kv_len, int mode, int kv_seq,
    int qld, int kvld)
{
    extern __shared__ float sm[];
    float* Qs = sm + QS_OFF;
    float* Ks = sm + KS_OFF;
    float* Vs = sm + VS_OFF;
    float* Ps = sm + PS_OFF;

    const int tid  = threadIdx.x;
    const int lane = tid & 31, warp = tid >> 5;
    const int g = lane >> 2, tg = lane & 3;
    const int h  = blockIdx.y;
    const int bf = blockIdx.z;
    const int q0 = blockIdx.x * 128;

    int frame0_row0, prev_row0 = 0;
    if (mode == 0) {
        const int f = vlp[0];
        const int b_idx = bf / f;
        const int fr = bf - b_idx * f;
        const int pf = (fr == 0) ? 0 : (fr - 1);
        frame0_row0 = (b_idx * f) * kv_seq;
        prev_row0   = (b_idx * f + pf) * kv_seq;
    } else {
        frame0_row0 = bf * kv_seq;
    }

    {
        const int srow = tid & 127;
        const int dh   = (tid >> 7) * 40;
        const float* qsrc = Q + ((size_t)bf * S_Q + q0 + srow) * qld + h * HD + dh;
        float* qdst = Qs + srow * QSTR + dh;
        #pragma unroll
        for (int i = 0; i < 10; i++) {
            const float4 v = *(const float4*)(qsrc + i * 4);
            qdst[i * 4 + 0] = to_tf32(v.x * ATTN_SCALE);
            qdst[i * 4 + 1] = to_tf32(v.y * ATTN_SCALE);
            qdst[i * 4 + 2] = to_tf32(v.z * ATTN_SCALE);
            qdst[i * 4 + 3] = to_tf32(v.w * ATTN_SCALE);
        }
    }

    float o[10][4];
    #pragma unroll
    for (int nt = 0; nt < 10; nt++)
        #pragma unroll
        for (int i = 0; i < 4; i++) o[nt][i] = 0.f;
    float m0 = NEG_BIG, m1 = NEG_BIG, l0 = 0.f, l1 = 0.f;

    const int kj = tid >> 2;
    const int kq = (tid & 3) * 20;

    const int ntiles = (kv_len + 63) >> 6;
    for (int t = 0; t < ntiles; t++) {
        const int kbase = t * 64;
        {
            const int jg = kbase + kj;
            const bool valid = jg < kv_len;
            int row = 0;
            if (valid) {
                if (mode == 0) row = (jg < kv_seq) ? (frame0_row0 + jg) : (prev_row0 + jg - kv_seq);
                else           row = frame0_row0 + jg;
            }
            const float* ksrc = Kbuf + (size_t)row * kvld + h * HD + kq;
            const float* vsrc = Vbuf + (size_t)row * kvld + h * HD + kq;
            float* vdst = Vs + kj * VSTR + kq;
            #pragma unroll
            for (int i = 0; i < 5; i++) {
                float4 kv = valid ? *(const float4*)(ksrc + i * 4) : make_float4(0.f,0.f,0.f,0.f);
                float4 vv = valid ? *(const float4*)(vsrc + i * 4) : make_float4(0.f,0.f,0.f,0.f);
                const int d = kq + i * 4;
                Ks[(d + 0) * KSTR + kj] = to_tf32(kv.x);
                Ks[(d + 1) * KSTR + kj] = to_tf32(kv.y);
                Ks[(d + 2) * KSTR + kj] = to_tf32(kv.z);
                Ks[(d + 3) * KSTR + kj] = to_tf32(kv.w);
                float4 vt = make_float4(to_tf32(vv.x), to_tf32(vv.y), to_tf32(vv.z), to_tf32(vv.w));
                *(float4*)(vdst + i * 4) = vt;
            }
        }
        __syncthreads();

        float s[8][4];
        #pragma unroll
        for (int nt = 0; nt < 8; nt++)
            #pragma unroll
            for (int i = 0; i < 4; i++) s[nt][i] = 0.f;

        #pragma unroll
        for (int k8 = 0; k8 < 10; k8++) {
            uint32_t af[4], bfg[8][2];
            const float* ap  = Qs + (warp * 16 + g) * QSTR + k8 * 8 + tg;
            af[0] = __float_as_uint(ap[0]);
            af[1] = __float_as_uint(ap[8 * QSTR]);
            af[2] = __float_as_uint(ap[4]);
            af[3] = __float_as_uint(ap[8 * QSTR + 4]);
            #pragma unroll
            for (int nt = 0; nt < 8; nt++) {
                const float* bp = Ks + (k8 * 8 + tg) * KSTR + nt * 8 + g;
                bfg[nt][0] = __float_as_uint(bp[0]);
                bfg[nt][1] = __float_as_uint(bp[4 * KSTR]);
            }
            #pragma unroll
            for (int nt = 0; nt < 8; nt++) mma_tf32(s[nt], af, bfg[nt]);
        }

        float mx0 = NEG_BIG, mx1 = NEG_BIG;
        #pragma unroll
        for (int nt = 0; nt < 8; nt++) {
            if (mode == 1) {
                const int c0 = kbase + nt * 8 + 2 * tg;
                if (c0 >= kv_len)     { s[nt][0] = NEG_BIG; s[nt][2] = NEG_BIG; }
                if (c0 + 1 >= kv_len) { s[nt][1] = NEG_BIG; s[nt][3] = NEG_BIG; }
            }
            mx0 = fmaxf(mx0, fmaxf(s[nt][0], s[nt][1]));
            mx1 = fmaxf(mx1, fmaxf(s[nt][2], s[nt][3]));
        }
        mx0 = fmaxf(mx0, __shfl_xor_sync(0xFFFFFFFFu, mx0, 1));
        mx0 = fmaxf(mx0, __shfl_xor_sync(0xFFFFFFFFu, mx0, 2));
        mx1 = fmaxf(mx1, __shfl_xor_sync(0xFFFFFFFFu, mx1, 1));
        mx1 = fmaxf(mx1, __shfl_xor_sync(0xFFFFFFFFu, mx1, 2));

        const float mn0 = fmaxf(m0, mx0), mn1 = fmaxf(m1, mx1);
        const float a0 = __expf(m0 - mn0), a1 = __expf(m1 - mn1);
        l0 *= a0; l1 *= a1;
        #pragma unroll
        for (int nt = 0; nt < 10; nt++) {
            o[nt][0] *= a0; o[nt][1] *= a0; o[nt][2] *= a1; o[nt][3] *= a1;
        }

        float ls0 = 0.f, ls1 = 0.f;
        {
            float* pr0 = Ps + (warp * 16 + g) * PSTR + 2 * tg;
            float* pr1 = pr0 + 8 * PSTR;
            #pragma unroll
            for (int nt = 0; nt < 8; nt++) {
                const float p0 = __expf(s[nt][0] - mn0);
                const float p1 = __expf(s[nt][1] - mn0);
                const float p2 = __expf(s[nt][2] - mn1);
                const float p3 = __expf(s[nt][3] - mn1);
                ls0 += p0 + p1; ls1 += p2 + p3;
                *(float2*)(pr0 + nt * 8) = make_float2(to_tf32(p0), to_tf32(p1));
                *(float2*)(pr1 + nt * 8) = make_float2(to_tf32(p2), to_tf32(p3));
            }
        }
        ls0 += __shfl_xor_sync(0xFFFFFFFFu, ls0, 1);
        ls0 += __shfl_xor_sync(0xFFFFFFFFu, ls0, 2);
        ls1 += __shfl_xor_sync(0xFFFFFFFFu, ls1, 1);
        ls1 += __shfl_xor_sync(0xFFFFFFFFu, ls1, 2);
        l0 += ls0; l1 += ls1;
        m0 = mn0; m1 = mn1;
        __syncwarp();

        #pragma unroll
        for (int k8 = 0; k8 < 8; k8++) {
            uint32_t af[4], bfg[10][2];
            const float* ap = Ps + (warp * 16 + g) * PSTR + k8 * 8 + tg;
            af[0] = __float_as_uint(ap[0]);
            af[1] = __float_as_uint(ap[8 * PSTR]);
            af[2] = __float_as_uint(ap[4]);
            af[3] = __float_as_uint(ap[8 * PSTR + 4]);
            #pragma unroll
            for (int nt = 0; nt < 10; nt++) {
                const float* bp = Vs + (k8 * 8 + tg) * VSTR + nt * 8 + g;
                bfg[nt][0] = __float_as_uint(bp[0]);
                bfg[nt][1] = __float_as_uint(bp[4 * VSTR]);
            }
            #pragma unroll
            for (int nt = 0; nt < 10; nt++) mma_tf32(o[nt], af, bfg[nt]);
        }
        __syncthreads();
    }

    const float inv0 = 1.0f / l0, inv1 = 1.0f / l1;
    const size_t r0 = (size_t)bf * S_Q + q0 + warp * 16 + g;
    const size_t r1 = r0 + 8;
    float* o0 = O + r0 * D_MODEL + h * HD + 2 * tg;
    float* o1 = O + r1 * D_MODEL + h * HD + 2 * tg;
    #pragma unroll
    for (int nt = 0; nt < 10; nt++) {
        *(float2*)(o0 + nt * 8) = make_float2(o[nt][0] * inv0, o[nt][1] * inv0);
        *(float2*)(o1 + nt * 8) = make_float2(o[nt][2] * inv1, o[nt][3] * inv1);
    }
}

// ---------------- host ----------------
static inline void run_gemm(const float* A, const float* B, const float* bias,
                            const float* resid, float* C, int M, int N, int K) {
    const int nTiles = (N / 128) * ((M + 127) / 128);
    const int nb = nTiles < PERSIST_BLOCKS ? nTiles : PERSIST_BLOCKS;
    gemm_tf32_kernel_t<0><<<nb, 256>>>(A, B, bias, resid, C, M, N, K);
}
static inline void run_gemm_gelu(const float* A, const float* B, const float* bias,
                                 float* C, int M, int N, int K) {
    const int nTiles = (N / 128) * ((M + 127) / 128);
    const int nb = nTiles < PERSIST_BLOCKS ? nTiles : PERSIST_BLOCKS;
    gemm_tf32_kernel_t<1><<<nb, 256>>>(A, B, bias, nullptr, C, M, N, K);
}

extern "C" void kernel_launch(void* const* d_in, const int* in_sizes, int n_in,
                              void* d_out, int out_size) {
    const float* hidden = (const float*)d_in[0];
    const float* enc    = (const float*)d_in[1];
    const int*   vl     = (const int*)d_in[2];
    const float* ln1_w  = (const float*)d_in[3];
    const float* ln1_b  = (const float*)d_in[4];
    const float* q1     = (const float*)d_in[5];
    const float* k1     = (const float*)d_in[6];
    const float* v1     = (const float*)d_in[7];
    const float* o1_w   = (const float*)d_in[8];
    const float* o1_b   = (const float*)d_in[9];
    const float* ln2_w  = (const float*)d_in[10];
    const float* ln2_b  = (const float*)d_in[11];
    const float* q2     = (const float*)d_in[12];
    const float* k2     = (const float*)d_in[13];
    const float* v2     = (const float*)d_in[14];
    const float* o2_w   = (const float*)d_in[15];
    const float* o2_b   = (const float*)d_in[16];
    const float* ln3_w  = (const float*)d_in[17];
    const float* ln3_b  = (const float*)d_in[18];
    const float* ff_w1  = (const float*)d_in[19];
    const float* ff_b1  = (const float*)d_in[20];
    const float* ff_w2  = (const float*)d_in[21];
    const float* ff_b2  = (const float*)d_in[22];
    float* out = (float*)d_out;

    const int BF   = in_sizes[0] / (S_Q * D_MODEL);          // 8
    const int ROWS = BF * S_Q;                               // 8192
    const int EB   = in_sizes[1] / (ENC_LEN * ENC_DIM);      // 8
    const int EROWS = EB * ENC_LEN;                          // 616

    static int attr_set = 0;
    if (!attr_set) {
        cudaFuncSetAttribute(attn_mma_kernel, cudaFuncAttributeMaxDynamicSharedMemorySize, ATTN_SMEM_BYTES);
        attr_set = 1;
    }

    float *x, *qkv, *q2b, *kvb, *ab, *h2, *h3, *gated, *wqkv, *wkv, *w1p, *b1p;
    cudaGetSymbolAddress((void**)&x,    g_x);
    cudaGetSymbolAddress((void**)&qkv,  g_qkv);
    cudaGetSymbolAddress((void**)&q2b,  g_q2);
    cudaGetSymbolAddress((void**)&kvb,  g_kv);
    cudaGetSymbolAddress((void**)&ab,   g_attn);
    cudaGetSymbolAddress((void**)&h2,   g_h2);
    cudaGetSymbolAddress((void**)&h3,   g_h3);
    cudaGetSymbolAddress((void**)&gated, g_gated);
    cudaGetSymbolAddress((void**)&wqkv, g_wqkv);
    cudaGetSymbolAddress((void**)&wkv,  g_wkv);
    cudaGetSymbolAddress((void**)&w1p,  g_w1p);
    cudaGetSymbolAddress((void**)&b1p,  g_b1p);

    // ---- pack weights ----
    {
        const int n3 = D_MODEL * D_MODEL;
        pack3_kernel<<<(n3 + 255) / 256, 256>>>(q1, k1, v1, wqkv, D_MODEL, D_MODEL);
        const int n2 = ENC_DIM * D_MODEL;
        pack2_kernel<<<(n2 + 255) / 256, 256>>>(k2, v2, wkv, ENC_DIM, D_MODEL);
        const int nw1 = D_MODEL * PROJ_N;
        packw1_kernel<<<(nw1 + 255) / 256, 256>>>(ff_w1, w1p);
        packb1_kernel<<<(PROJ_N + 255) / 256, 256>>>(ff_b1, b1p);
    }

    // ---- block 1: self-attn with temporal KV gather ----
    ln_kernel<<<ROWS, 256>>>(hidden, ln1_w, ln1_b, x);
    run_gemm(x, wqkv, nullptr, nullptr, qkv, ROWS, 3 * D_MODEL, D_MODEL);
    {
        dim3 grid(S_Q / 128, N_HEADS, BF);
        attn_mma_kernel<<<grid, 256, ATTN_SMEM_BYTES>>>(
            qkv, qkv + D_MODEL, qkv + 2 * D_MODEL, ab, vl,
            2 * S_Q, 0, S_Q, 3 * D_MODEL, 3 * D_MODEL);
    }
    run_gemm(ab, o1_w, o1_b, hidden, h2, ROWS, D_MODEL, D_MODEL);

    // ---- block 2: cross attention ----
    ln_kernel<<<ROWS, 256>>>(h2, ln2_w, ln2_b, x);
    run_gemm(x, q2, nullptr, nullptr, q2b, ROWS, D_MODEL, D_MODEL);
    run_gemm(enc, wkv, nullptr, nullptr, kvb, EROWS, 2 * D_MODEL, ENC_DIM);
    {
        dim3 grid(S_Q / 128, N_HEADS, BF);
        attn_mma_kernel<<<grid, 256, ATTN_SMEM_BYTES>>>(
            q2b, kvb, kvb + D_MODEL, ab, vl,
            ENC_LEN, 1, ENC_LEN, D_MODEL, 2 * D_MODEL);
    }
    run_gemm(ab, o2_w, o2_b, h2, h3, ROWS, D_MODEL, D_MODEL);

    // ---- block 3: fused gated-GeLU FF ----
    ln_kernel<<<ROWS, 256>>>(h3, ln3_w, ln3_b, x);
    run_gemm_gelu(x, w1p, b1p, gated, ROWS, PROJ_N, D_MODEL);
    run_gemm(gated, ff_w2, ff_b2, h3, out, ROWS, D_MODEL, FF_IN);
}

// round 13
// speedup vs baseline: 1.0614x; 1.0614x over previous
#include <cuda_runtime.h>
#include <cuda_bf16.h>
#include <math.h>
#include <stdint.h>

// ---------------- problem constants ----------------
#define S_Q      1024
#define D_MODEL  640
#define N_HEADS  8
#define HD       80
#define ENC_LEN  77
#define ENC_DIM  768
#define FF_IN    2560
#define PROJ_N   5120
#define BF_MAX   8
#define ROWS_MAX (BF_MAX * S_Q)
#define ATTN_SCALE 0.11180339887498949f
#define NEG_BIG  -3.0e38f

// ---------------- scratch ----------------
__device__ float g_x[ROWS_MAX * D_MODEL];
__device__ float g_qkv[ROWS_MAX * 3 * D_MODEL];
__device__ float g_q2[ROWS_MAX * D_MODEL];
__device__ float g_kv[1024 * 2 * D_MODEL];
__device__ float g_attn[ROWS_MAX * D_MODEL];
__device__ float g_h2[ROWS_MAX * D_MODEL];
__device__ float g_h3[ROWS_MAX * D_MODEL];
__device__ float g_gated[ROWS_MAX * FF_IN];
__device__ float g_wqkv[D_MODEL * 3 * D_MODEL];
__device__ float g_wkv[ENC_DIM * 2 * D_MODEL];
__device__ float g_w1p[D_MODEL * PROJ_N];       // interleaved (h, gate) ff_w1
__device__ float g_b1p[PROJ_N];                 // interleaved ff bias

// ---------------- mma / cp.async helpers ----------------
__device__ __forceinline__ float to_tf32(float x) {
    uint32_t r;
    asm("cvt.rna.tf32.f32 %0, %1;" : "=r"(r) : "f"(x));
    return __uint_as_float(r);
}
__device__ __forceinline__ void mma_tf32(float c[4], const uint32_t a[4], const uint32_t b[2]) {
    asm volatile(
        "mma.sync.aligned.m16n8k8.row.col.f32.tf32.tf32.f32 "
        "{%0,%1,%2,%3}, {%4,%5,%6,%7}, {%8,%9}, {%0,%1,%2,%3};"
        : "+f"(c[0]), "+f"(c[1]), "+f"(c[2]), "+f"(c[3])
        : "r"(a[0]), "r"(a[1]), "r"(a[2]), "r"(a[3]), "r"(b[0]), "r"(b[1]));
}
__device__ __forceinline__ void cp16(float* smem, const float* gmem) {
    uint32_t a = (uint32_t)__cvta_generic_to_shared(smem);
    asm volatile("cp.async.cg.shared.global [%0], [%1], 16;" :: "r"(a), "l"(gmem));
}
#define CP_COMMIT() asm volatile("cp.async.commit_group;")
#define CP_WAIT2()  asm volatile("cp.async.wait_group 2;")

// gelu(g) = 0.5*g*(1+tanh(0.79788456*(g+0.044715 g^3))) = g / (1 + exp(-2u))
__device__ __forceinline__ float gelu_tanh(float g) {
    const float u = 0.7978845608028654f * (g + 0.044715f * g * g * g);
    return g * __frcp_rn(1.0f + __expf(-2.0f * u));
}

// ---------------- weight packing ----------------
__global__ void pack3_kernel(const float* __restrict__ a, const float* __restrict__ b,
                             const float* __restrict__ c, float* __restrict__ out,
                             int rows, int cols) {
    const int idx = blockIdx.x * blockDim.x + threadIdx.x;
    if (idx >= rows * cols) return;
    const int r = idx / cols, j = idx - r * cols;
    float* o = out + (size_t)r * 3 * cols;
    o[j] = a[idx]; o[cols + j] = b[idx]; o[2 * cols + j] = c[idx];
}
__global__ void pack2_kernel(const float* __restrict__ a, const float* __restrict__ b,
                             float* __restrict__ out, int rows, int cols) {
    const int idx = blockIdx.x * blockDim.x + threadIdx.x;
    if (idx >= rows * cols) return;
    const int r = idx / cols, j = idx - r * cols;
    float* o = out + (size_t)r * 2 * cols;
    o[j] = a[idx]; o[cols + j] = b[idx];
}
// interleave ff_w1 (+ bias folded into same launch):
// out col 2j = h-col j, col 2j+1 = gate-col j
__global__ void packw1_kernel(const float* __restrict__ w, float* __restrict__ out,
                              const float* __restrict__ b, float* __restrict__ bout) {
    const int idx = blockIdx.x * blockDim.x + threadIdx.x;
    if (idx < PROJ_N) {
        const int jb = idx >> 1, sb = idx & 1;
        bout[idx] = b[sb * FF_IN + jb];
    }
    if (idx >= D_MODEL * PROJ_N) return;
    const int k = idx / PROJ_N, c = idx - k * PROJ_N;
    const int j = c >> 1, s = c & 1;
    out[idx] = w[(size_t)k * PROJ_N + s * FF_IN + j];
}

// ---------------- LayerNorm: warp-per-row, fully vectorized ----------------
// 256 threads = 8 warps = 8 rows per block; lane handles 20 cols as 5 float4.
__global__ __launch_bounds__(256) void ln_kernel(
    const float* __restrict__ x, const float* __restrict__ w,
    const float* __restrict__ b, float* __restrict__ out, int rows) {
    const int warp = threadIdx.x >> 5, lane = threadIdx.x & 31;
    const int row = blockIdx.x * 8 + warp;
    if (row >= rows) return;
    const float* xr = x + (size_t)row * D_MODEL;
    float* orow = out + (size_t)row * D_MODEL;

    float4 v[5];
    float s = 0.f, s2 = 0.f;
    #pragma unroll
    for (int i = 0; i < 5; i++) {
        v[i] = *(const float4*)(xr + i * 128 + lane * 4);
        s  += v[i].x + v[i].y + v[i].z + v[i].w;
        s2 += v[i].x * v[i].x + v[i].y * v[i].y + v[i].z * v[i].z + v[i].w * v[i].w;
    }
    #pragma unroll
    for (int o = 16; o; o >>= 1) {
        s  += __shfl_xor_sync(0xFFFFFFFFu, s,  o);
        s2 += __shfl_xor_sync(0xFFFFFFFFu, s2, o);
    }
    const float mean = s * (1.0f / D_MODEL);
    const float var  = s2 * (1.0f / D_MODEL) - mean * mean;
    const float rstd = rsqrtf(var + 1e-5f);
    #pragma unroll
    for (int i = 0; i < 5; i++) {
        const int c = i * 128 + lane * 4;
        const float4 wv = *(const float4*)(w + c);
        const float4 bv = *(const float4*)(b + c);
        float4 ov;
        ov.x = (v[i].x - mean) * rstd * wv.x + bv.x;
        ov.y = (v[i].y - mean) * rstd * wv.y + bv.y;
        ov.z = (v[i].z - mean) * rstd * wv.z + bv.z;
        ov.w = (v[i].w - mean) * rstd * wv.w + bv.w;
        *(float4*)(orow + c) = ov;
    }
}

// ---------------- tf32 GEMM: 128x128 block, 8 warps, warp 32x64, BK16, 4-stage ----------------
#define ASTR 20
#define BSTR 136
#define GSTAGES 4

template<int GELU_FUSE>
__global__ __launch_bounds__(256, 2) void gemm_tf32_kernel_t(
    const float* __restrict__ A, const float* __restrict__ B,
    const float* __restrict__ bias, const float* __restrict__ resid,
    float* __restrict__ C, int M, int N, int K)
{
    __shared__ float As[GSTAGES][128 * ASTR];
    __shared__ float Bs[GSTAGES][16 * BSTR];

    const int tid  = threadIdx.x;
    const int lane = tid & 31, warp = tid >> 5;
    const int wm = warp & 3, wn = warp >> 2;
    const int g  = lane >> 2, tg = lane & 3;
    const int bm = blockIdx.y * 128, bn = blockIdx.x * 128;

    const int ar0 = (tid * 2) >> 2, ac0 = ((tid * 2) & 3) * 4;
    const int ar1 = (tid * 2 + 1) >> 2, ac1 = ((tid * 2 + 1) & 3) * 4;
    const int br0 = (tid * 2) >> 5, bc0 = ((tid * 2) & 31) * 4;
    const int br1 = (tid * 2 + 1) >> 5, bc1 = ((tid * 2 + 1) & 31) * 4;

    const float* Ap0 = A + (size_t)min(bm + ar0, M - 1) * K + ac0;
    const float* Ap1 = A + (size_t)min(bm + ar1, M - 1) * K + ac1;
    const float* Bp0 = B + (size_t)br0 * N + bn + bc0;
    const float* Bp1 = B + (size_t)br1 * N + bn + bc1;

    float acc[2][8][4];
    #pragma unroll
    for (int mt = 0; mt < 2; mt++)
        #pragma unroll
        for (int nt = 0; nt < 8; nt++)
            #pragma unroll
            for (int i = 0; i < 4; i++) acc[mt][nt][i] = 0.f;

    const int T = K >> 4;

    #pragma unroll
    for (int s = 0; s < GSTAGES - 1; s++) {
        if (s < T) {
            cp16(&As[s][ar0 * ASTR + ac0], Ap0 + s * 16);
            cp16(&As[s][ar1 * ASTR + ac1], Ap1 + s * 16);
            cp16(&Bs[s][br0 * BSTR + bc0], Bp0 + (size_t)s * 16 * N);
            cp16(&Bs[s][br1 * BSTR + bc1], Bp1 + (size_t)s * 16 * N);
        }
        CP_COMMIT();
    }

    for (int t = 0; t < T; t++) {
        CP_WAIT2();
        __syncthreads();

        const int cur = t & (GSTAGES - 1);
        const float* as = As[cur];
        const float* bs = Bs[cur];
        #pragma unroll
        for (int k8 = 0; k8 < 2; k8++) {
            uint32_t af[2][4], bf[8][2];
            #pragma unroll
            for (int mt = 0; mt < 2; mt++) {
                const float* p  = as + (wm * 32 + mt * 16 + g) * ASTR + k8 * 8 + tg;
                const float* p8 = p + 8 * ASTR;
                af[mt][0] = __float_as_uint(p[0]);
                af[mt][1] = __float_as_uint(p8[0]);
                af[mt][2] = __float_as_uint(p[4]);
                af[mt][3] = __float_as_uint(p8[4]);
            }
            #pragma unroll
            for (int nt = 0; nt < 8; nt++) {
                const float* p = bs + (k8 * 8 + tg) * BSTR + wn * 64 + nt * 8 + g;
                bf[nt][0] = __float_as_uint(p[0]);
                bf[nt][1] = __float_as_uint(p[4 * BSTR]);
            }
            #pragma unroll
            for (int mt = 0; mt < 2; mt++)
                #pragma unroll
                for (int nt = 0; nt < 8; nt++)
                    mma_tf32(acc[mt][nt], af[mt], bf[nt]);
        }

        const int tn = t + GSTAGES - 1;
        if (tn < T) {
            const int nxt = tn & (GSTAGES - 1);
            cp16(&As[nxt][ar0 * ASTR + ac0], Ap0 + tn * 16);
            cp16(&As[nxt][ar1 * ASTR + ac1], Ap1 + tn * 16);
            cp16(&Bs[nxt][br0 * BSTR + bc0], Bp0 + (size_t)tn * 16 * N);
            cp16(&Bs[nxt][br1 * BSTR + bc1], Bp1 + (size_t)tn * 16 * N);
        }
        CP_COMMIT();
    }

    if (GELU_FUSE) {
        const int NO = N >> 1;
        #pragma unroll
        for (int nt = 0; nt < 8; nt++) {
            const int c = bn + wn * 64 + nt * 8 + tg * 2;
            const float2 bv = *(const float2*)(bias + c);
            const int j = c >> 1;
            #pragma unroll
            for (int mt = 0; mt < 2; mt++) {
                const int r0 = bm + wm * 32 + mt * 16 + g;
                if (r0 < M)
                    C[(size_t)r0 * NO + j] = (acc[mt][nt][0] + bv.x) * gelu_tanh(acc[mt][nt][1] + bv.y);
                const int r1 = r0 + 8;
                if (r1 < M)
                    C[(size_t)r1 * NO + j] = (acc[mt][nt][2] + bv.x) * gelu_tanh(acc[mt][nt][3] + bv.y);
            }
        }
    } else {
        #pragma unroll
        for (int nt = 0; nt < 8; nt++) {
            const int c = bn + wn * 64 + nt * 8 + tg * 2;
            float bx = 0.f, by = 0.f;
            if (bias) { const float2 bv = *(const float2*)(bias + c); bx = bv.x; by = bv.y; }
            #pragma unroll
            for (int mt = 0; mt < 2; mt++) {
                const int r0 = bm + wm * 32 + mt * 16 + g;
                if (r0 < M) {
                    float2 v = make_float2(acc[mt][nt][0] + bx, acc[mt][nt][1] + by);
                    if (resid) { const float2 rv = *(const float2*)(resid + (size_t)r0 * N + c); v.x += rv.x; v.y += rv.y; }
                    *(float2*)(C + (size_t)r0 * N + c) = v;
                }
                const int r1 = r0 + 8;
                if (r1 < M) {
                    float2 v = make_float2(acc[mt][nt][2] + bx, acc[mt][nt][3] + by);
                    if (resid) { const float2 rv = *(const float2*)(resid + (size_t)r1 * N + c); v.x += rv.x; v.y += rv.y; }
                    *(float2*)(C + (size_t)r1 * N + c) = v;
                }
            }
        }
    }
}

// ---------------- tf32 MMA flash attention: 128-query tile, 8 warps ----------------
#define QSTR 84
#define KSTR 72
#define VSTR 88
#define PSTR 76
#define QS_OFF 0
#define KS_OFF (128 * QSTR)
#define VS_OFF (KS_OFF + 80 * KSTR)
#define PS_OFF (VS_OFF + 64 * VSTR)
#define ATTN_SMEM_FLOATS (PS_OFF + 128 * PSTR)
#define ATTN_SMEM_BYTES  (ATTN_SMEM_FLOATS * 4)

__global__ __launch_bounds__(256, 1) void attn_mma_kernel(
    const float* __restrict__ Q, const float* __restrict__ Kbuf,
    const float* __restrict__ Vbuf, float* __restrict__ O,
    const int* __restrict__ vlp, int kv_len, int mode, int kv_seq,
    int qld, int kvld)
{
    extern __shared__ float sm[];
    float* Qs = sm + QS_OFF;
    float* Ks = sm + KS_OFF;
    float* Vs = sm + VS_OFF;
    float* Ps = sm + PS_OFF;

    const int tid  = threadIdx.x;
    const int lane = tid & 31, warp = tid >> 5;
    const int g = lane >> 2, tg = lane & 3;
    const int h  = blockIdx.y;
    const int bf = blockIdx.z;
    const int q0 = blockIdx.x * 128;

    int frame0_row0, prev_row0 = 0;
    if (mode == 0) {
        const int f = vlp[0];
        const int b_idx = bf / f;
        const int fr = bf - b_idx * f;
        const int pf = (fr == 0) ? 0 : (fr - 1);
        frame0_row0 = (b_idx * f) * kv_seq;
        prev_row0   = (b_idx * f + pf) * kv_seq;
    } else {
        frame0_row0 = bf * kv_seq;
    }

    {
        const int srow = tid & 127;
        const int dh   = (tid >> 7) * 40;
        const float* qsrc = Q + ((size_t)bf * S_Q + q0 + srow) * qld + h * HD + dh;
        float* qdst = Qs + srow * QSTR + dh;
        #pragma unroll
        for (int i = 0; i < 10; i++) {
            const float4 v = *(const float4*)(qsrc + i * 4);
            qdst[i * 4 + 0] = to_tf32(v.x * ATTN_SCALE);
            qdst[i * 4 + 1] = to_tf32(v.y * ATTN_SCALE);
            qdst[i * 4 + 2] = to_tf32(v.z * ATTN_SCALE);
            qdst[i * 4 + 3] = to_tf32(v.w * ATTN_SCALE);
        }
    }

    float o[10][4];
    #pragma unroll
    for (int nt = 0; nt < 10; nt++)
        #pragma unroll
        for (int i = 0; i < 4; i++) o[nt][i] = 0.f;
    float m0 = NEG_BIG, m1 = NEG_BIG, l0 = 0.f, l1 = 0.f;

    const int kj = tid >> 2;
    const int kq = (tid & 3) * 20;

    const int ntiles = (kv_len + 63) >> 6;
    for (int t = 0; t < ntiles; t++) {
        const int kbase = t * 64;
        {
            const int jg = kbase + kj;
            const bool valid = jg < kv_len;
            int row = 0;
            if (valid) {
                if (mode == 0) row = (jg < kv_seq) ? (frame0_row0 + jg) : (prev_row0 + jg - kv_seq);
                else           row = frame0_row0 + jg;
            }
            const float* ksrc = Kbuf + (size_t)row * kvld + h * HD + kq;
            const float* vsrc = Vbuf + (size_t)row * kvld + h * HD + kq;
            float* vdst = Vs + kj * VSTR + kq;
            #pragma unroll
            for (int i = 0; i < 5; i++) {
                float4 kv = valid ? *(const float4*)(ksrc + i * 4) : make_float4(0.f,0.f,0.f,0.f);
                float4 vv = valid ? *(const float4*)(vsrc + i * 4) : make_float4(0.f,0.f,0.f,0.f);
                const int d = kq + i * 4;
                Ks[(d + 0) * KSTR + kj] = to_tf32(kv.x);
                Ks[(d + 1) * KSTR + kj] = to_tf32(kv.y);
                Ks[(d + 2) * KSTR + kj] = to_tf32(kv.z);
                Ks[(d + 3) * KSTR + kj] = to_tf32(kv.w);
                float4 vt = make_float4(to_tf32(vv.x), to_tf32(vv.y), to_tf32(vv.z), to_tf32(vv.w));
                *(float4*)(vdst + i * 4) = vt;
            }
        }
        __syncthreads();

        float s[8][4];
        #pragma unroll
        for (int nt = 0; nt < 8; nt++)
            #pragma unroll
            for (int i = 0; i < 4; i++) s[nt][i] = 0.f;

        #pragma unroll
        for (int k8 = 0; k8 < 10; k8++) {
            uint32_t af[4], bfg[8][2];
            const float* ap  = Qs + (warp * 16 + g) * QSTR + k8 * 8 + tg;
            af[0] = __float_as_uint(ap[0]);
            af[1] = __float_as_uint(ap[8 * QSTR]);
            af[2] = __float_as_uint(ap[4]);
            af[3] = __float_as_uint(ap[8 * QSTR + 4]);
            #pragma unroll
            for (int nt = 0; nt < 8; nt++) {
                const float* bp = Ks + (k8 * 8 + tg) * KSTR + nt * 8 + g;
                bfg[nt][0] = __float_as_uint(bp[0]);
                bfg[nt][1] = __float_as_uint(bp[4 * KSTR]);
            }
            #pragma unroll
            for (int nt = 0; nt < 8; nt++) mma_tf32(s[nt], af, bfg[nt]);
        }

        float mx0 = NEG_BIG, mx1 = NEG_BIG;
        #pragma unroll
        for (int nt = 0; nt < 8; nt++) {
            if (mode == 1) {
                const int c0 = kbase + nt * 8 + 2 * tg;
                if (c0 >= kv_len)     { s[nt][0] = NEG_BIG; s[nt][2] = NEG_BIG; }
                if (c0 + 1 >= kv_len) { s[nt][1] = NEG_BIG; s[nt][3] = NEG_BIG; }
            }
            mx0 = fmaxf(mx0, fmaxf(s[nt][0], s[nt][1]));
            mx1 = fmaxf(mx1, fmaxf(s[nt][2], s[nt][3]));
        }
        mx0 = fmaxf(mx0, __shfl_xor_sync(0xFFFFFFFFu, mx0, 1));
        mx0 = fmaxf(mx0, __shfl_xor_sync(0xFFFFFFFFu, mx0, 2));
        mx1 = fmaxf(mx1, __shfl_xor_sync(0xFFFFFFFFu, mx1, 1));
        mx1 = fmaxf(mx1, __shfl_xor_sync(0xFFFFFFFFu, mx1, 2));

        const float mn0 = fmaxf(m0, mx0), mn1 = fmaxf(m1, mx1);
        const float a0 = __expf(m0 - mn0), a1 = __expf(m1 - mn1);
        l0 *= a0; l1 *= a1;
        #pragma unroll
        for (int nt = 0; nt < 10; nt++) {
            o[nt][0] *= a0; o[nt][1] *= a0; o[nt][2] *= a1; o[nt][3] *= a1;
        }

        float ls0 = 0.f, ls1 = 0.f;
        {
            float* pr0 = Ps + (warp * 16 + g) * PSTR + 2 * tg;
            float* pr1 = pr0 + 8 * PSTR;
            #pragma unroll
            for (int nt = 0; nt < 8; nt++) {
                const float p0 = __expf(s[nt][0] - mn0);
                const float p1 = __expf(s[nt][1] - mn0);
                const float p2 = __expf(s[nt][2] - mn1);
                const float p3 = __expf(s[nt][3] - mn1);
                ls0 += p0 + p1; ls1 += p2 + p3;
                *(float2*)(pr0 + nt * 8) = make_float2(to_tf32(p0), to_tf32(p1));
                *(float2*)(pr1 + nt * 8) = make_float2(to_tf32(p2), to_tf32(p3));
            }
        }
        ls0 += __shfl_xor_sync(0xFFFFFFFFu, ls0, 1);
        ls0 += __shfl_xor_sync(0xFFFFFFFFu, ls0, 2);
        ls1 += __shfl_xor_sync(0xFFFFFFFFu, ls1, 1);
        ls1 += __shfl_xor_sync(0xFFFFFFFFu, ls1, 2);
        l0 += ls0; l1 += ls1;
        m0 = mn0; m1 = mn1;
        __syncwarp();

        #pragma unroll
        for (int k8 = 0; k8 < 8; k8++) {
            uint32_t af[4], bfg[10][2];
            const float* ap = Ps + (warp * 16 + g) * PSTR + k8 * 8 + tg;
            af[0] = __float_as_uint(ap[0]);
            af[1] = __float_as_uint(ap[8 * PSTR]);
            af[2] = __float_as_uint(ap[4]);
            af[3] = __float_as_uint(ap[8 * PSTR + 4]);
            #pragma unroll
            for (int nt = 0; nt < 10; nt++) {
                const float* bp = Vs + (k8 * 8 + tg) * VSTR + nt * 8 + g;
                bfg[nt][0] = __float_as_uint(bp[0]);
                bfg[nt][1] = __float_as_uint(bp[4 * VSTR]);
            }
            #pragma unroll
            for (int nt = 0; nt < 10; nt++) mma_tf32(o[nt], af, bfg[nt]);
        }
        __syncthreads();
    }

    const float inv0 = 1.0f / l0, inv1 = 1.0f / l1;
    const size_t r0 = (size_t)bf * S_Q + q0 + warp * 16 + g;
    const size_t r1 = r0 + 8;
    float* o0 = O + r0 * D_MODEL + h * HD + 2 * tg;
    float* o1 = O + r1 * D_MODEL + h * HD + 2 * tg;
    #pragma unroll
    for (int nt = 0; nt < 10; nt++) {
        *(float2*)(o0 + nt * 8) = make_float2(o[nt][0] * inv0, o[nt][1] * inv0);
        *(float2*)(o1 + nt * 8) = make_float2(o[nt][2] * inv1, o[nt][3] * inv1);
    }
}

// ---------------- host ----------------
static inline void run_gemm(const float* A, const float* B, const float* bias,
                            const float* resid, float* C, int M, int N, int K) {
    dim3 grid(N / 128, (M + 127) / 128);
    gemm_tf32_kernel_t<0><<<grid, 256>>>(A, B, bias, resid, C, M, N, K);
}
static inline void run_gemm_gelu(const float* A, const float* B, const float* bias,
                                 float* C, int M, int N, int K) {
    dim3 grid(N / 128, (M + 127) / 128);
    gemm_tf32_kernel_t<1><<<grid, 256>>>(A, B, bias, nullptr, C, M, N, K);
}
static inline void run_ln(const float* x, const float* w, const float* b,
                          float* out, int rows) {
    ln_kernel<<<(rows + 7) / 8, 256>>>(x, w, b, out, rows);
}

extern "C" void kernel_launch(void* const* d_in, const int* in_sizes, int n_in,
                              void* d_out, int out_size) {
    const float* hidden = (const float*)d_in[0];
    const float* enc    = (const float*)d_in[1];
    const int*   vl     = (const int*)d_in[2];
    const float* ln1_w  = (const float*)d_in[3];
    const float* ln1_b  = (const float*)d_in[4];
    const float* q1     = (const float*)d_in[5];
    const float* k1     = (const float*)d_in[6];
    const float* v1     = (const float*)d_in[7];
    const float* o1_w   = (const float*)d_in[8];
    const float* o1_b   = (const float*)d_in[9];
    const float* ln2_w  = (const float*)d_in[10];
    const float* ln2_b  = (const float*)d_in[11];
    const float* q2     = (const float*)d_in[12];
    const float* k2     = (const float*)d_in[13];
    const float* v2     = (const float*)d_in[14];
    const float* o2_w   = (const float*)d_in[15];
    const float* o2_b   = (const float*)d_in[16];
    const float* ln3_w  = (const float*)d_in[17];
    const float* ln3_b  = (const float*)d_in[18];
    const float* ff_w1  = (const float*)d_in[19];
    const float* ff_b1  = (const float*)d_in[20];
    const float* ff_w2  = (const float*)d_in[21];
    const float* ff_b2  = (const float*)d_in[22];
    float* out = (float*)d_out;

    const int BF   = in_sizes[0] / (S_Q * D_MODEL);          // 8
    const int ROWS = BF * S_Q;                               // 8192
    const int EB   = in_sizes[1] / (ENC_LEN * ENC_DIM);      // 8
    const int EROWS = EB * ENC_LEN;                          // 616

    static int attr_set = 0;
    if (!attr_set) {
        cudaFuncSetAttribute(attn_mma_kernel, cudaFuncAttributeMaxDynamicSharedMemorySize, ATTN_SMEM_BYTES);
        attr_set = 1;
    }

    float *x, *qkv, *q2b, *kvb, *ab, *h2, *h3, *gated, *wqkv, *wkv, *w1p, *b1p;
    cudaGetSymbolAddress((void**)&x,    g_x);
    cudaGetSymbolAddress((void**)&qkv,  g_qkv);
    cudaGetSymbolAddress((void**)&q2b,  g_q2);
    cudaGetSymbolAddress((void**)&kvb,  g_kv);
    cudaGetSymbolAddress((void**)&ab,   g_attn);
    cudaGetSymbolAddress((void**)&h2,   g_h2);
    cudaGetSymbolAddress((void**)&h3,   g_h3);
    cudaGetSymbolAddress((void**)&gated, g_gated);
    cudaGetSymbolAddress((void**)&wqkv, g_wqkv);
    cudaGetSymbolAddress((void**)&wkv,  g_wkv);
    cudaGetSymbolAddress((void**)&w1p,  g_w1p);
    cudaGetSymbolAddress((void**)&b1p,  g_b1p);

    // ---- pack weights ----
    {
        const int n3 = D_MODEL * D_MODEL;
        pack3_kernel<<<(n3 + 255) / 256, 256>>>(q1, k1, v1, wqkv, D_MODEL, D_MODEL);
        const int n2 = ENC_DIM * D_MODEL;
        pack2_kernel<<<(n2 + 255) / 256, 256>>>(k2, v2, wkv, ENC_DIM, D_MODEL);
        const int nw1 = D_MODEL * PROJ_N;
        packw1_kernel<<<(nw1 + 255) / 256, 256>>>(ff_w1, w1p, ff_b1, b1p);
    }

    // ---- block 1: self-attn with temporal KV gather ----
    run_ln(hidden, ln1_w, ln1_b, x, ROWS);
    run_gemm(x, wqkv, nullptr, nullptr, qkv, ROWS, 3 * D_MODEL, D_MODEL);
    {
        dim3 grid(S_Q / 128, N_HEADS, BF);
        attn_mma_kernel<<<grid, 256, ATTN_SMEM_BYTES>>>(
            qkv, qkv + D_MODEL, qkv + 2 * D_MODEL, ab, vl,
            2 * S_Q, 0, S_Q, 3 * D_MODEL, 3 * D_MODEL);
    }
    run_gemm(ab, o1_w, o1_b, hidden, h2, ROWS, D_MODEL, D_MODEL);

    // ---- block 2: cross attention ----
    run_ln(h2, ln2_w, ln2_b, x, ROWS);
    run_gemm(x, q2, nullptr, nullptr, q2b, ROWS, D_MODEL, D_MODEL);
    run_gemm(enc, wkv, nullptr, nullptr, kvb, EROWS, 2 * D_MODEL, ENC_DIM);
    {
        dim3 grid(S_Q / 128, N_HEADS, BF);
        attn_mma_kernel<<<grid, 256, ATTN_SMEM_BYTES>>>(
            q2b, kvb, kvb + D_MODEL, ab, vl,
            ENC_LEN, 1, ENC_LEN, D_MODEL, 2 * D_MODEL);
    }
    run_gemm(ab, o2_w, o2_b, h2, h3, ROWS, D_MODEL, D_MODEL);

    // ---- block 3: fused gated-GeLU FF ----
    run_ln(h3, ln3_w, ln3_b, x, ROWS);
    run_gemm_gelu(x, w1p, b1p, gated, ROWS, PROJ_N, D_MODEL);
    run_gemm(gated, ff_w2, ff_b2, h3, out, ROWS, D_MODEL, FF_IN);
}

// round 14
// speedup vs baseline: 1.0820x; 1.0194x over previous
#include <cuda_runtime.h>
#include <cuda_bf16.h>
#include <math.h>
#include <stdint.h>

// ---------------- problem constants ----------------
#define S_Q      1024
#define D_MODEL  640
#define N_HEADS  8
#define HD       80
#define ENC_LEN  77
#define ENC_DIM  768
#define FF_IN    2560
#define PROJ_N   5120
#define BF_MAX   8
#define ROWS_MAX (BF_MAX * S_Q)
#define ATTN_SCALE 0.11180339887498949f
#define NEG_BIG  -3.0e38f

// ---------------- scratch ----------------
__device__ float g_x[ROWS_MAX * D_MODEL];
__device__ float g_qkv[ROWS_MAX * 3 * D_MODEL];
__device__ float g_q2[ROWS_MAX * D_MODEL];
__device__ float g_kv[1024 * 2 * D_MODEL];
__device__ float g_attn[ROWS_MAX * D_MODEL];
__device__ float g_h2[ROWS_MAX * D_MODEL];
__device__ float g_h3[ROWS_MAX * D_MODEL];
__device__ float g_gated[ROWS_MAX * FF_IN];
__device__ float g_wqkv[D_MODEL * 3 * D_MODEL];
__device__ float g_wkv[ENC_DIM * 2 * D_MODEL];
__device__ float g_w1p[D_MODEL * PROJ_N];
__device__ float g_b1p[PROJ_N];

// ---------------- mma / cp.async helpers ----------------
__device__ __forceinline__ float to_tf32(float x) {
    uint32_t r;
    asm("cvt.rna.tf32.f32 %0, %1;" : "=r"(r) : "f"(x));
    return __uint_as_float(r);
}
__device__ __forceinline__ void mma_tf32(float c[4], const uint32_t a[4], const uint32_t b[2]) {
    asm volatile(
        "mma.sync.aligned.m16n8k8.row.col.f32.tf32.tf32.f32 "
        "{%0,%1,%2,%3}, {%4,%5,%6,%7}, {%8,%9}, {%0,%1,%2,%3};"
        : "+f"(c[0]), "+f"(c[1]), "+f"(c[2]), "+f"(c[3])
        : "r"(a[0]), "r"(a[1]), "r"(a[2]), "r"(a[3]), "r"(b[0]), "r"(b[1]));
}
__device__ __forceinline__ void cp16(float* smem, const float* gmem) {
    uint32_t a = (uint32_t)__cvta_generic_to_shared(smem);
    asm volatile("cp.async.cg.shared.global [%0], [%1], 16;" :: "r"(a), "l"(gmem));
}
#define CP_COMMIT() asm volatile("cp.async.commit_group;")
#define CP_WAIT2()  asm volatile("cp.async.wait_group 2;")

__device__ __forceinline__ float gelu_tanh(float g) {
    const float u = 0.7978845608028654f * (g + 0.044715f * g * g * g);
    return g * __frcp_rn(1.0f + __expf(-2.0f * u));
}

// ---------------- weight packing ----------------
__global__ void pack3_kernel(const float* __restrict__ a, const float* __restrict__ b,
                             const float* __restrict__ c, float* __restrict__ out,
                             int rows, int cols) {
    const int idx = blockIdx.x * blockDim.x + threadIdx.x;
    if (idx >= rows * cols) return;
    const int r = idx / cols, j = idx - r * cols;
    float* o = out + (size_t)r * 3 * cols;
    o[j] = a[idx]; o[cols + j] = b[idx]; o[2 * cols + j] = c[idx];
}
__global__ void pack2_kernel(const float* __restrict__ a, const float* __restrict__ b,
                             float* __restrict__ out, int rows, int cols) {
    const int idx = blockIdx.x * blockDim.x + threadIdx.x;
    if (idx >= rows * cols) return;
    const int r = idx / cols, j = idx - r * cols;
    float* o = out + (size_t)r * 2 * cols;
    o[j] = a[idx]; o[cols + j] = b[idx];
}
__global__ void packw1_kernel(const float* __restrict__ w, float* __restrict__ out,
                              const float* __restrict__ b, float* __restrict__ bout) {
    const int idx = blockIdx.x * blockDim.x + threadIdx.x;
    if (idx < PROJ_N) {
        const int jb = idx >> 1, sb = idx & 1;
        bout[idx] = b[sb * FF_IN + jb];
    }
    if (idx >= D_MODEL * PROJ_N) return;
    const int k = idx / PROJ_N, c = idx - k * PROJ_N;
    const int j = c >> 1, s = c & 1;
    out[idx] = w[(size_t)k * PROJ_N + s * FF_IN + j];
}

// ---------------- LayerNorm: warp-per-row, vectorized ----------------
__global__ __launch_bounds__(256) void ln_kernel(
    const float* __restrict__ x, const float* __restrict__ w,
    const float* __restrict__ b, float* __restrict__ out, int rows) {
    const int warp = threadIdx.x >> 5, lane = threadIdx.x & 31;
    const int row = blockIdx.x * 8 + warp;
    if (row >= rows) return;
    const float* xr = x + (size_t)row * D_MODEL;
    float* orow = out + (size_t)row * D_MODEL;

    float4 v[5];
    float s = 0.f, s2 = 0.f;
    #pragma unroll
    for (int i = 0; i < 5; i++) {
        v[i] = *(const float4*)(xr + i * 128 + lane * 4);
        s  += v[i].x + v[i].y + v[i].z + v[i].w;
        s2 += v[i].x * v[i].x + v[i].y * v[i].y + v[i].z * v[i].z + v[i].w * v[i].w;
    }
    #pragma unroll
    for (int o = 16; o; o >>= 1) {
        s  += __shfl_xor_sync(0xFFFFFFFFu, s,  o);
        s2 += __shfl_xor_sync(0xFFFFFFFFu, s2, o);
    }
    const float mean = s * (1.0f / D_MODEL);
    const float var  = s2 * (1.0f / D_MODEL) - mean * mean;
    const float rstd = rsqrtf(var + 1e-5f);
    #pragma unroll
    for (int i = 0; i < 5; i++) {
        const int c = i * 128 + lane * 4;
        const float4 wv = *(const float4*)(w + c);
        const float4 bv = *(const float4*)(b + c);
        float4 ov;
        ov.x = (v[i].x - mean) * rstd * wv.x + bv.x;
        ov.y = (v[i].y - mean) * rstd * wv.y + bv.y;
        ov.z = (v[i].z - mean) * rstd * wv.z + bv.z;
        ov.w = (v[i].w - mean) * rstd * wv.w + bv.w;
        *(float4*)(orow + c) = ov;
    }
}

// ---------------- tf32 GEMM: 128x128 block, 8 warps, warp 32x64, BK16, 4-stage ----------------
#define ASTR 20
#define BSTR 136
#define GSTAGES 4

template<int GELU_FUSE>
__global__ __launch_bounds__(256, 2) void gemm_tf32_kernel_t(
    const float* __restrict__ A, const float* __restrict__ B,
    const float* __restrict__ bias, const float* __restrict__ resid,
    float* __restrict__ C, int M, int N, int K)
{
    __shared__ float As[GSTAGES][128 * ASTR];
    __shared__ float Bs[GSTAGES][16 * BSTR];

    const int tid  = threadIdx.x;
    const int lane = tid & 31, warp = tid >> 5;
    const int wm = warp & 3, wn = warp >> 2;
    const int g  = lane >> 2, tg = lane & 3;
    const int bm = blockIdx.y * 128, bn = blockIdx.x * 128;

    const int ar0 = (tid * 2) >> 2, ac0 = ((tid * 2) & 3) * 4;
    const int ar1 = (tid * 2 + 1) >> 2, ac1 = ((tid * 2 + 1) & 3) * 4;
    const int br0 = (tid * 2) >> 5, bc0 = ((tid * 2) & 31) * 4;
    const int br1 = (tid * 2 + 1) >> 5, bc1 = ((tid * 2 + 1) & 31) * 4;

    const float* Ap0 = A + (size_t)min(bm + ar0, M - 1) * K + ac0;
    const float* Ap1 = A + (size_t)min(bm + ar1, M - 1) * K + ac1;
    const float* Bp0 = B + (size_t)br0 * N + bn + bc0;
    const float* Bp1 = B + (size_t)br1 * N + bn + bc1;

    float acc[2][8][4];
    #pragma unroll
    for (int mt = 0; mt < 2; mt++)
        #pragma unroll
        for (int nt = 0; nt < 8; nt++)
            #pragma unroll
            for (int i = 0; i < 4; i++) acc[mt][nt][i] = 0.f;

    const int T = K >> 4;

    #pragma unroll
    for (int s = 0; s < GSTAGES - 1; s++) {
        if (s < T) {
            cp16(&As[s][ar0 * ASTR + ac0], Ap0 + s * 16);
            cp16(&As[s][ar1 * ASTR + ac1], Ap1 + s * 16);
            cp16(&Bs[s][br0 * BSTR + bc0], Bp0 + (size_t)s * 16 * N);
            cp16(&Bs[s][br1 * BSTR + bc1], Bp1 + (size_t)s * 16 * N);
        }
        CP_COMMIT();
    }

    for (int t = 0; t < T; t++) {
        CP_WAIT2();
        __syncthreads();

        const int cur = t & (GSTAGES - 1);
        const float* as = As[cur];
        const float* bs = Bs[cur];
        #pragma unroll
        for (int k8 = 0; k8 < 2; k8++) {
            uint32_t af[2][4], bf[8][2];
            #pragma unroll
            for (int mt = 0; mt < 2; mt++) {
                const float* p  = as + (wm * 32 + mt * 16 + g) * ASTR + k8 * 8 + tg;
                const float* p8 = p + 8 * ASTR;
                af[mt][0] = __float_as_uint(p[0]);
                af[mt][1] = __float_as_uint(p8[0]);
                af[mt][2] = __float_as_uint(p[4]);
                af[mt][3] = __float_as_uint(p8[4]);
            }
            #pragma unroll
            for (int nt = 0; nt < 8; nt++) {
                const float* p = bs + (k8 * 8 + tg) * BSTR + wn * 64 + nt * 8 + g;
                bf[nt][0] = __float_as_uint(p[0]);
                bf[nt][1] = __float_as_uint(p[4 * BSTR]);
            }
            #pragma unroll
            for (int mt = 0; mt < 2; mt++)
                #pragma unroll
                for (int nt = 0; nt < 8; nt++)
                    mma_tf32(acc[mt][nt], af[mt], bf[nt]);
        }

        const int tn = t + GSTAGES - 1;
        if (tn < T) {
            const int nxt = tn & (GSTAGES - 1);
            cp16(&As[nxt][ar0 * ASTR + ac0], Ap0 + tn * 16);
            cp16(&As[nxt][ar1 * ASTR + ac1], Ap1 + tn * 16);
            cp16(&Bs[nxt][br0 * BSTR + bc0], Bp0 + (size_t)tn * 16 * N);
            cp16(&Bs[nxt][br1 * BSTR + bc1], Bp1 + (size_t)tn * 16 * N);
        }
        CP_COMMIT();
    }

    if (GELU_FUSE) {
        const int NO = N >> 1;
        #pragma unroll
        for (int nt = 0; nt < 8; nt++) {
            const int c = bn + wn * 64 + nt * 8 + tg * 2;
            const float2 bv = *(const float2*)(bias + c);
            const int j = c >> 1;
            #pragma unroll
            for (int mt = 0; mt < 2; mt++) {
                const int r0 = bm + wm * 32 + mt * 16 + g;
                if (r0 < M)
                    C[(size_t)r0 * NO + j] = (acc[mt][nt][0] + bv.x) * gelu_tanh(acc[mt][nt][1] + bv.y);
                const int r1 = r0 + 8;
                if (r1 < M)
                    C[(size_t)r1 * NO + j] = (acc[mt][nt][2] + bv.x) * gelu_tanh(acc[mt][nt][3] + bv.y);
            }
        }
    } else {
        #pragma unroll
        for (int nt = 0; nt < 8; nt++) {
            const int c = bn + wn * 64 + nt * 8 + tg * 2;
            float bx = 0.f, by = 0.f;
            if (bias) { const float2 bv = *(const float2*)(bias + c); bx = bv.x; by = bv.y; }
            #pragma unroll
            for (int mt = 0; mt < 2; mt++) {
                const int r0 = bm + wm * 32 + mt * 16 + g;
                if (r0 < M) {
                    float2 v = make_float2(acc[mt][nt][0] + bx, acc[mt][nt][1] + by);
                    if (resid) { const float2 rv = *(const float2*)(resid + (size_t)r0 * N + c); v.x += rv.x; v.y += rv.y; }
                    *(float2*)(C + (size_t)r0 * N + c) = v;
                }
                const int r1 = r0 + 8;
                if (r1 < M) {
                    float2 v = make_float2(acc[mt][nt][2] + bx, acc[mt][nt][3] + by);
                    if (resid) { const float2 rv = *(const float2*)(resid + (size_t)r1 * N + c); v.x += rv.x; v.y += rv.y; }
                    *(float2*)(C + (size_t)r1 * N + c) = v;
                }
            }
        }
    }
}

// ---------------- tf32 MMA flash attention: 128-query tile, 8 warps ----------------
#define QSTR 84
#define KSTR 72
#define VSTR 88
#define PSTR 76
#define QS_OFF 0
#define KS_OFF (128 * QSTR)
#define VS_OFF (KS_OFF + 80 * KSTR)
#define PS_OFF (VS_OFF + 64 * VSTR)
#define ATTN_SMEM_FLOATS (PS_OFF + 128 * PSTR)
#define ATTN_SMEM_BYTES  (ATTN_SMEM_FLOATS * 4)

__global__ __launch_bounds__(256, 1) void attn_mma_kernel(
    const float* __restrict__ Q, const float* __restrict__ Kbuf,
    const float* __restrict__ Vbuf, float* __restrict__ O,
    const int* __restrict__ vlp, int kv_len, int mode, int kv_seq,
    int qld, int kvld)
{
    extern __shared__ float sm[];
    float* Qs = sm + QS_OFF;
    float* Ks = sm + KS_OFF;
    float* Vs = sm + VS_OFF;
    float* Ps = sm + PS_OFF;

    const int tid  = threadIdx.x;
    const int lane = tid & 31, warp = tid >> 5;
    const int g = lane >> 2, tg = lane & 3;
    const int h  = blockIdx.y;
    const int bf = blockIdx.z;
    const int q0 = blockIdx.x * 128;

    int frame0_row0, prev_row0 = 0;
    if (mode == 0) {
        const int f = vlp[0];
        const int b_idx = bf / f;
        const int fr = bf - b_idx * f;
        const int pf = (fr == 0) ? 0 : (fr - 1);
        frame0_row0 = (b_idx * f) * kv_seq;
        prev_row0   = (b_idx * f + pf) * kv_seq;
    } else {
        frame0_row0 = bf * kv_seq;
    }

    {
        const int srow = tid & 127;
        const int dh   = (tid >> 7) * 40;
        const float* qsrc = Q + ((size_t)bf * S_Q + q0 + srow) * qld + h * HD + dh;
        float* qdst = Qs + srow * QSTR + dh;
        #pragma unroll
        for (int i = 0; i < 10; i++) {
            const float4 v = *(const float4*)(qsrc + i * 4);
            qdst[i * 4 + 0] = to_tf32(v.x * ATTN_SCALE);
            qdst[i * 4 + 1] = to_tf32(v.y * ATTN_SCALE);
            qdst[i * 4 + 2] = to_tf32(v.z * ATTN_SCALE);
            qdst[i * 4 + 3] = to_tf32(v.w * ATTN_SCALE);
        }
    }

    float o[10][4];
    #pragma unroll
    for (int nt = 0; nt < 10; nt++)
        #pragma unroll
        for (int i = 0; i < 4; i++) o[nt][i] = 0.f;
    float m0 = NEG_BIG, m1 = NEG_BIG, l0 = 0.f, l1 = 0.f;

    const int kj = tid >> 2;
    const int kq = (tid & 3) * 20;

    const int ntiles = (kv_len + 63) >> 6;
    for (int t = 0; t < ntiles; t++) {
        const int kbase = t * 64;
        {
            const int jg = kbase + kj;
            const bool valid = jg < kv_len;
            int row = 0;
            if (valid) {
                if (mode == 0) row = (jg < kv_seq) ? (frame0_row0 + jg) : (prev_row0 + jg - kv_seq);
                else           row = frame0_row0 + jg;
            }
            const float* ksrc = Kbuf + (size_t)row * kvld + h * HD + kq;
            const float* vsrc = Vbuf + (size_t)row * kvld + h * HD + kq;
            float* vdst = Vs + kj * VSTR + kq;
            #pragma unroll
            for (int i = 0; i < 5; i++) {
                float4 kv = valid ? *(const float4*)(ksrc + i * 4) : make_float4(0.f,0.f,0.f,0.f);
                float4 vv = valid ? *(const float4*)(vsrc + i * 4) : make_float4(0.f,0.f,0.f,0.f);
                const int d = kq + i * 4;
                Ks[(d + 0) * KSTR + kj] = to_tf32(kv.x);
                Ks[(d + 1) * KSTR + kj] = to_tf32(kv.y);
                Ks[(d + 2) * KSTR + kj] = to_tf32(kv.z);
                Ks[(d + 3) * KSTR + kj] = to_tf32(kv.w);
                float4 vt = make_float4(to_tf32(vv.x), to_tf32(vv.y), to_tf32(vv.z), to_tf32(vv.w));
                *(float4*)(vdst + i * 4) = vt;
            }
        }
        __syncthreads();

        float s[8][4];
        #pragma unroll
        for (int nt = 0; nt < 8; nt++)
            #pragma unroll
            for (int i = 0; i < 4; i++) s[nt][i] = 0.f;

        #pragma unroll
        for (int k8 = 0; k8 < 10; k8++) {
            uint32_t af[4], bfg[8][2];
            const float* ap  = Qs + (warp * 16 + g) * QSTR + k8 * 8 + tg;
            af[0] = __float_as_uint(ap[0]);
            af[1] = __float_as_uint(ap[8 * QSTR]);
            af[2] = __float_as_uint(ap[4]);
            af[3] = __float_as_uint(ap[8 * QSTR + 4]);
            #pragma unroll
            for (int nt = 0; nt < 8; nt++) {
                const float* bp = Ks + (k8 * 8 + tg) * KSTR + nt * 8 + g;
                bfg[nt][0] = __float_as_uint(bp[0]);
                bfg[nt][1] = __float_as_uint(bp[4 * KSTR]);
            }
            #pragma unroll
            for (int nt = 0; nt < 8; nt++) mma_tf32(s[nt], af, bfg[nt]);
        }

        float mx0 = NEG_BIG, mx1 = NEG_BIG;
        #pragma unroll
        for (int nt = 0; nt < 8; nt++) {
            if (mode == 1) {
                const int c0 = kbase + nt * 8 + 2 * tg;
                if (c0 >= kv_len)     { s[nt][0] = NEG_BIG; s[nt][2] = NEG_BIG; }
                if (c0 + 1 >= kv_len) { s[nt][1] = NEG_BIG; s[nt][3] = NEG_BIG; }
            }
            mx0 = fmaxf(mx0, fmaxf(s[nt][0], s[nt][1]));
            mx1 = fmaxf(mx1, fmaxf(s[nt][2], s[nt][3]));
        }
        mx0 = fmaxf(mx0, __shfl_xor_sync(0xFFFFFFFFu, mx0, 1));
        mx0 = fmaxf(mx0, __shfl_xor_sync(0xFFFFFFFFu, mx0, 2));
        mx1 = fmaxf(mx1, __shfl_xor_sync(0xFFFFFFFFu, mx1, 1));
        mx1 = fmaxf(mx1, __shfl_xor_sync(0xFFFFFFFFu, mx1, 2));

        const float mn0 = fmaxf(m0, mx0), mn1 = fmaxf(m1, mx1);
        const float a0 = __expf(m0 - mn0), a1 = __expf(m1 - mn1);
        l0 *= a0; l1 *= a1;
        #pragma unroll
        for (int nt = 0; nt < 10; nt++) {
            o[nt][0] *= a0; o[nt][1] *= a0; o[nt][2] *= a1; o[nt][3] *= a1;
        }

        float ls0 = 0.f, ls1 = 0.f;
        {
            float* pr0 = Ps + (warp * 16 + g) * PSTR + 2 * tg;
            float* pr1 = pr0 + 8 * PSTR;
            #pragma unroll
            for (int nt = 0; nt < 8; nt++) {
                const float p0 = __expf(s[nt][0] - mn0);
                const float p1 = __expf(s[nt][1] - mn0);
                const float p2 = __expf(s[nt][2] - mn1);
                const float p3 = __expf(s[nt][3] - mn1);
                ls0 += p0 + p1; ls1 += p2 + p3;
                *(float2*)(pr0 + nt * 8) = make_float2(to_tf32(p0), to_tf32(p1));
                *(float2*)(pr1 + nt * 8) = make_float2(to_tf32(p2), to_tf32(p3));
            }
        }
        ls0 += __shfl_xor_sync(0xFFFFFFFFu, ls0, 1);
        ls0 += __shfl_xor_sync(0xFFFFFFFFu, ls0, 2);
        ls1 += __shfl_xor_sync(0xFFFFFFFFu, ls1, 1);
        ls1 += __shfl_xor_sync(0xFFFFFFFFu, ls1, 2);
        l0 += ls0; l1 += ls1;
        m0 = mn0; m1 = mn1;
        __syncwarp();

        #pragma unroll
        for (int k8 = 0; k8 < 8; k8++) {
            uint32_t af[4], bfg[10][2];
            const float* ap = Ps + (warp * 16 + g) * PSTR + k8 * 8 + tg;
            af[0] = __float_as_uint(ap[0]);
            af[1] = __float_as_uint(ap[8 * PSTR]);
            af[2] = __float_as_uint(ap[4]);
            af[3] = __float_as_uint(ap[8 * PSTR + 4]);
            #pragma unroll
            for (int nt = 0; nt < 10; nt++) {
                const float* bp = Vs + (k8 * 8 + tg) * VSTR + nt * 8 + g;
                bfg[nt][0] = __float_as_uint(bp[0]);
                bfg[nt][1] = __float_as_uint(bp[4 * VSTR]);
            }
            #pragma unroll
            for (int nt = 0; nt < 10; nt++) mma_tf32(o[nt], af, bfg[nt]);
        }
        __syncthreads();
    }

    const float inv0 = 1.0f / l0, inv1 = 1.0f / l1;
    const size_t r0 = (size_t)bf * S_Q + q0 + warp * 16 + g;
    const size_t r1 = r0 + 8;
    float* o0 = O + r0 * D_MODEL + h * HD + 2 * tg;
    float* o1 = O + r1 * D_MODEL + h * HD + 2 * tg;
    #pragma unroll
    for (int nt = 0; nt < 10; nt++) {
        *(float2*)(o0 + nt * 8) = make_float2(o[nt][0] * inv0, o[nt][1] * inv0);
        *(float2*)(o1 + nt * 8) = make_float2(o[nt][2] * inv1, o[nt][3] * inv1);
    }
}

// ---------------- host ----------------
static inline void run_gemm_s(cudaStream_t st, const float* A, const float* B, const float* bias,
                              const float* resid, float* C, int M, int N, int K) {
    dim3 grid(N / 128, (M + 127) / 128);
    gemm_tf32_kernel_t<0><<<grid, 256, 0, st>>>(A, B, bias, resid, C, M, N, K);
}
static inline void run_gemm(const float* A, const float* B, const float* bias,
                            const float* resid, float* C, int M, int N, int K) {
    run_gemm_s(0, A, B, bias, resid, C, M, N, K);
}
static inline void run_gemm_gelu(const float* A, const float* B, const float* bias,
                                 float* C, int M, int N, int K) {
    dim3 grid(N / 128, (M + 127) / 128);
    gemm_tf32_kernel_t<1><<<grid, 256>>>(A, B, bias, nullptr, C, M, N, K);
}
static inline void run_ln(const float* x, const float* w, const float* b,
                          float* out, int rows) {
    ln_kernel<<<(rows + 7) / 8, 256>>>(x, w, b, out, rows);
}

extern "C" void kernel_launch(void* const* d_in, const int* in_sizes, int n_in,
                              void* d_out, int out_size) {
    const float* hidden = (const float*)d_in[0];
    const float* enc    = (const float*)d_in[1];
    const int*   vl     = (const int*)d_in[2];
    const float* ln1_w  = (const float*)d_in[3];
    const float* ln1_b  = (const float*)d_in[4];
    const float* q1     = (const float*)d_in[5];
    const float* k1     = (const float*)d_in[6];
    const float* v1     = (const float*)d_in[7];
    const float* o1_w   = (const float*)d_in[8];
    const float* o1_b   = (const float*)d_in[9];
    const float* ln2_w  = (const float*)d_in[10];
    const float* ln2_b  = (const float*)d_in[11];
    const float* q2     = (const float*)d_in[12];
    const float* k2     = (const float*)d_in[13];
    const float* v2     = (const float*)d_in[14];
    const float* o2_w   = (const float*)d_in[15];
    const float* o2_b   = (const float*)d_in[16];
    const float* ln3_w  = (const float*)d_in[17];
    const float* ln3_b  = (const float*)d_in[18];
    const float* ff_w1  = (const float*)d_in[19];
    const float* ff_b1  = (const float*)d_in[20];
    const float* ff_w2  = (const float*)d_in[21];
    const float* ff_b2  = (const float*)d_in[22];
    float* out = (float*)d_out;

    const int BF   = in_sizes[0] / (S_Q * D_MODEL);          // 8
    const int ROWS = BF * S_Q;                               // 8192
    const int EB   = in_sizes[1] / (ENC_LEN * ENC_DIM);      // 8
    const int EROWS = EB * ENC_LEN;                          // 616

    static int init_done = 0;
    static cudaStream_t s_side = nullptr;
    static cudaEvent_t evRoot = nullptr, evPack = nullptr, evKV = nullptr;
    if (!init_done) {
        cudaFuncSetAttribute(attn_mma_kernel, cudaFuncAttributeMaxDynamicSharedMemorySize, ATTN_SMEM_BYTES);
        cudaStreamCreateWithFlags(&s_side, cudaStreamNonBlocking);
        cudaEventCreateWithFlags(&evRoot, cudaEventDisableTiming);
        cudaEventCreateWithFlags(&evPack, cudaEventDisableTiming);
        cudaEventCreateWithFlags(&evKV,   cudaEventDisableTiming);
        init_done = 1;
    }

    float *x, *qkv, *q2b, *kvb, *ab, *h2, *h3, *gated, *wqkv, *wkv, *w1p, *b1p;
    cudaGetSymbolAddress((void**)&x,    g_x);
    cudaGetSymbolAddress((void**)&qkv,  g_qkv);
    cudaGetSymbolAddress((void**)&q2b,  g_q2);
    cudaGetSymbolAddress((void**)&kvb,  g_kv);
    cudaGetSymbolAddress((void**)&ab,   g_attn);
    cudaGetSymbolAddress((void**)&h2,   g_h2);
    cudaGetSymbolAddress((void**)&h3,   g_h3);
    cudaGetSymbolAddress((void**)&gated, g_gated);
    cudaGetSymbolAddress((void**)&wqkv, g_wqkv);
    cudaGetSymbolAddress((void**)&wkv,  g_wkv);
    cudaGetSymbolAddress((void**)&w1p,  g_w1p);
    cudaGetSymbolAddress((void**)&b1p,  g_b1p);

    // ---- fork: side stream does packs + kv2 GEMM; main does ln1 ----
    cudaEventRecord(evRoot, 0);
    cudaStreamWaitEvent(s_side, evRoot, 0);
    {
        const int n3 = D_MODEL * D_MODEL;
        pack3_kernel<<<(n3 + 255) / 256, 256, 0, s_side>>>(q1, k1, v1, wqkv, D_MODEL, D_MODEL);
        const int n2 = ENC_DIM * D_MODEL;
        pack2_kernel<<<(n2 + 255) / 256, 256, 0, s_side>>>(k2, v2, wkv, ENC_DIM, D_MODEL);
        const int nw1 = D_MODEL * PROJ_N;
        packw1_kernel<<<(nw1 + 255) / 256, 256, 0, s_side>>>(ff_w1, w1p, ff_b1, b1p);
    }
    cudaEventRecord(evPack, s_side);
    // kv2 GEMM on side stream (only needs enc + wkv); overlaps entire block 1
    run_gemm_s(s_side, enc, wkv, nullptr, nullptr, kvb, EROWS, 2 * D_MODEL, ENC_DIM);
    cudaEventRecord(evKV, s_side);

    // ---- block 1: self-attn with temporal KV gather ----
    run_ln(hidden, ln1_w, ln1_b, x, ROWS);
    cudaStreamWaitEvent(0, evPack, 0);       // qkv GEMM needs wqkv
    run_gemm(x, wqkv, nullptr, nullptr, qkv, ROWS, 3 * D_MODEL, D_MODEL);
    {
        dim3 grid(S_Q / 128, N_HEADS, BF);
        attn_mma_kernel<<<grid, 256, ATTN_SMEM_BYTES>>>(
            qkv, qkv + D_MODEL, qkv + 2 * D_MODEL, ab, vl,
            2 * S_Q, 0, S_Q, 3 * D_MODEL, 3 * D_MODEL);
    }
    run_gemm(ab, o1_w, o1_b, hidden, h2, ROWS, D_MODEL, D_MODEL);

    // ---- block 2: cross attention ----
    run_ln(h2, ln2_w, ln2_b, x, ROWS);
    run_gemm(x, q2, nullptr, nullptr, q2b, ROWS, D_MODEL, D_MODEL);
    cudaStreamWaitEvent(0, evKV, 0);         // cross-attn needs kv2 output
    {
        dim3 grid(S_Q / 128, N_HEADS, BF);
        attn_mma_kernel<<<grid, 256, ATTN_SMEM_BYTES>>>(
            q2b, kvb, kvb + D_MODEL, ab, vl,
            ENC_LEN, 1, ENC_LEN, D_MODEL, 2 * D_MODEL);
    }
    run_gemm(ab, o2_w, o2_b, h2, h3, ROWS, D_MODEL, D_MODEL);

    // ---- block 3: fused gated-GeLU FF ----
    run_ln(h3, ln3_w, ln3_b, x, ROWS);
    run_gemm_gelu(x, w1p, b1p, gated, ROWS, PROJ_N, D_MODEL);
    run_gemm(gated, ff_w2, ff_b2, h3, out, ROWS, D_MODEL, FF_IN);
}

// round 15
// speedup vs baseline: 1.0830x; 1.0009x over previous
#include <cuda_runtime.h>
#include <cuda_bf16.h>
#include <math.h>
#include <stdint.h>

// ---------------- problem constants ----------------
#define S_Q      1024
#define D_MODEL  640
#define N_HEADS  8
#define HD       80
#define ENC_LEN  77
#define ENC_DIM  768
#define FF_IN    2560
#define PROJ_N   5120
#define BF_MAX   8
#define ROWS_MAX (BF_MAX * S_Q)
#define ATTN_SCALE 0.11180339887498949f
#define NEG_BIG  -3.0e38f

// ---------------- scratch ----------------
__device__ float g_x[ROWS_MAX * D_MODEL];
__device__ float g_qkv[ROWS_MAX * 3 * D_MODEL];
__device__ float g_q2[ROWS_MAX * D_MODEL];
__device__ float g_kv[1024 * 2 * D_MODEL];
__device__ float g_attn[ROWS_MAX * D_MODEL];
__device__ float g_h2[ROWS_MAX * D_MODEL];
__device__ float g_h3[ROWS_MAX * D_MODEL];
__device__ float g_gated[ROWS_MAX * FF_IN];
__device__ float g_wqkv[D_MODEL * 3 * D_MODEL];
__device__ float g_wkv[ENC_DIM * 2 * D_MODEL];
__device__ float g_w1p[D_MODEL * PROJ_N];
__device__ float g_b1p[PROJ_N];

// ---------------- mma / cp.async helpers ----------------
__device__ __forceinline__ float to_tf32(float x) {
    uint32_t r;
    asm("cvt.rna.tf32.f32 %0, %1;" : "=r"(r) : "f"(x));
    return __uint_as_float(r);
}
__device__ __forceinline__ void mma_tf32(float c[4], const uint32_t a[4], const uint32_t b[2]) {
    asm volatile(
        "mma.sync.aligned.m16n8k8.row.col.f32.tf32.tf32.f32 "
        "{%0,%1,%2,%3}, {%4,%5,%6,%7}, {%8,%9}, {%0,%1,%2,%3};"
        : "+f"(c[0]), "+f"(c[1]), "+f"(c[2]), "+f"(c[3])
        : "r"(a[0]), "r"(a[1]), "r"(a[2]), "r"(a[3]), "r"(b[0]), "r"(b[1]));
}
__device__ __forceinline__ void cp16(float* smem, const float* gmem) {
    uint32_t a = (uint32_t)__cvta_generic_to_shared(smem);
    asm volatile("cp.async.cg.shared.global [%0], [%1], 16;" :: "r"(a), "l"(gmem));
}
#define CP_COMMIT() asm volatile("cp.async.commit_group;")
#define CP_WAIT2()  asm volatile("cp.async.wait_group 2;")

__device__ __forceinline__ float gelu_tanh(float g) {
    const float u = 0.7978845608028654f * (g + 0.044715f * g * g * g);
    return g * __frcp_rn(1.0f + __expf(-2.0f * u));
}

// ---------------- weight packing ----------------
__global__ void pack3_kernel(const float* __restrict__ a, const float* __restrict__ b,
                             const float* __restrict__ c, float* __restrict__ out,
                             int rows, int cols) {
    const int idx = blockIdx.x * blockDim.x + threadIdx.x;
    if (idx >= rows * cols) return;
    const int r = idx / cols, j = idx - r * cols;
    float* o = out + (size_t)r * 3 * cols;
    o[j] = a[idx]; o[cols + j] = b[idx]; o[2 * cols + j] = c[idx];
}
__global__ void pack2_kernel(const float* __restrict__ a, const float* __restrict__ b,
                             float* __restrict__ out, int rows, int cols) {
    const int idx = blockIdx.x * blockDim.x + threadIdx.x;
    if (idx >= rows * cols) return;
    const int r = idx / cols, j = idx - r * cols;
    float* o = out + (size_t)r * 2 * cols;
    o[j] = a[idx]; o[cols + j] = b[idx];
}
__global__ void packw1_kernel(const float* __restrict__ w, float* __restrict__ out,
                              const float* __restrict__ b, float* __restrict__ bout) {
    const int idx = blockIdx.x * blockDim.x + threadIdx.x;
    if (idx < PROJ_N) {
        const int jb = idx >> 1, sb = idx & 1;
        bout[idx] = b[sb * FF_IN + jb];
    }
    if (idx >= D_MODEL * PROJ_N) return;
    const int k = idx / PROJ_N, c = idx - k * PROJ_N;
    const int j = c >> 1, s = c & 1;
    out[idx] = w[(size_t)k * PROJ_N + s * FF_IN + j];
}

// ---------------- LayerNorm: warp-per-row, vectorized ----------------
__global__ __launch_bounds__(256) void ln_kernel(
    const float* __restrict__ x, const float* __restrict__ w,
    const float* __restrict__ b, float* __restrict__ out, int rows) {
    const int warp = threadIdx.x >> 5, lane = threadIdx.x & 31;
    const int row = blockIdx.x * 8 + warp;
    if (row >= rows) return;
    const float* xr = x + (size_t)row * D_MODEL;
    float* orow = out + (size_t)row * D_MODEL;

    float4 v[5];
    float s = 0.f, s2 = 0.f;
    #pragma unroll
    for (int i = 0; i < 5; i++) {
        v[i] = *(const float4*)(xr + i * 128 + lane * 4);
        s  += v[i].x + v[i].y + v[i].z + v[i].w;
        s2 += v[i].x * v[i].x + v[i].y * v[i].y + v[i].z * v[i].z + v[i].w * v[i].w;
    }
    #pragma unroll
    for (int o = 16; o; o >>= 1) {
        s  += __shfl_xor_sync(0xFFFFFFFFu, s,  o);
        s2 += __shfl_xor_sync(0xFFFFFFFFu, s2, o);
    }
    const float mean = s * (1.0f / D_MODEL);
    const float var  = s2 * (1.0f / D_MODEL) - mean * mean;
    const float rstd = rsqrtf(var + 1e-5f);
    #pragma unroll
    for (int i = 0; i < 5; i++) {
        const int c = i * 128 + lane * 4;
        const float4 wv = *(const float4*)(w + c);
        const float4 bv = *(const float4*)(b + c);
        float4 ov;
        ov.x = (v[i].x - mean) * rstd * wv.x + bv.x;
        ov.y = (v[i].y - mean) * rstd * wv.y + bv.y;
        ov.z = (v[i].z - mean) * rstd * wv.z + bv.z;
        ov.w = (v[i].w - mean) * rstd * wv.w + bv.w;
        *(float4*)(orow + c) = ov;
    }
}

// ---------------- tf32 GEMM: 128x128 block, 8 warps, warp 32x64, BK16, 4-stage ----------------
#define ASTR 20
#define BSTR 136
#define GSTAGES 4

template<int GELU_FUSE>
__global__ __launch_bounds__(256, 2) void gemm_tf32_kernel_t(
    const float* __restrict__ A, const float* __restrict__ B,
    const float* __restrict__ bias, const float* __restrict__ resid,
    float* __restrict__ C, int M, int N, int K)
{
    __shared__ float As[GSTAGES][128 * ASTR];
    __shared__ float Bs[GSTAGES][16 * BSTR];

    const int tid  = threadIdx.x;
    const int lane = tid & 31, warp = tid >> 5;
    const int wm = warp & 3, wn = warp >> 2;
    const int g  = lane >> 2, tg = lane & 3;
    const int bm = blockIdx.y * 128, bn = blockIdx.x * 128;

    const int ar0 = (tid * 2) >> 2, ac0 = ((tid * 2) & 3) * 4;
    const int ar1 = (tid * 2 + 1) >> 2, ac1 = ((tid * 2 + 1) & 3) * 4;
    const int br0 = (tid * 2) >> 5, bc0 = ((tid * 2) & 31) * 4;
    const int br1 = (tid * 2 + 1) >> 5, bc1 = ((tid * 2 + 1) & 31) * 4;

    const float* Ap0 = A + (size_t)min(bm + ar0, M - 1) * K + ac0;
    const float* Ap1 = A + (size_t)min(bm + ar1, M - 1) * K + ac1;
    const float* Bp0 = B + (size_t)br0 * N + bn + bc0;
    const float* Bp1 = B + (size_t)br1 * N + bn + bc1;

    float acc[2][8][4];
    #pragma unroll
    for (int mt = 0; mt < 2; mt++)
        #pragma unroll
        for (int nt = 0; nt < 8; nt++)
            #pragma unroll
            for (int i = 0; i < 4; i++) acc[mt][nt][i] = 0.f;

    const int T = K >> 4;

    #pragma unroll
    for (int s = 0; s < GSTAGES - 1; s++) {
        if (s < T) {
            cp16(&As[s][ar0 * ASTR + ac0], Ap0 + s * 16);
            cp16(&As[s][ar1 * ASTR + ac1], Ap1 + s * 16);
            cp16(&Bs[s][br0 * BSTR + bc0], Bp0 + (size_t)s * 16 * N);
            cp16(&Bs[s][br1 * BSTR + bc1], Bp1 + (size_t)s * 16 * N);
        }
        CP_COMMIT();
    }

    for (int t = 0; t < T; t++) {
        CP_WAIT2();
        __syncthreads();

        const int cur = t & (GSTAGES - 1);
        const float* as = As[cur];
        const float* bs = Bs[cur];
        #pragma unroll
        for (int k8 = 0; k8 < 2; k8++) {
            uint32_t af[2][4], bf[8][2];
            #pragma unroll
            for (int mt = 0; mt < 2; mt++) {
                const float* p  = as + (wm * 32 + mt * 16 + g) * ASTR + k8 * 8 + tg;
                const float* p8 = p + 8 * ASTR;
                af[mt][0] = __float_as_uint(p[0]);
                af[mt][1] = __float_as_uint(p8[0]);
                af[mt][2] = __float_as_uint(p[4]);
                af[mt][3] = __float_as_uint(p8[4]);
            }
            #pragma unroll
            for (int nt = 0; nt < 8; nt++) {
                const float* p = bs + (k8 * 8 + tg) * BSTR + wn * 64 + nt * 8 + g;
                bf[nt][0] = __float_as_uint(p[0]);
                bf[nt][1] = __float_as_uint(p[4 * BSTR]);
            }
            #pragma unroll
            for (int mt = 0; mt < 2; mt++)
                #pragma unroll
                for (int nt = 0; nt < 8; nt++)
                    mma_tf32(acc[mt][nt], af[mt], bf[nt]);
        }

        const int tn = t + GSTAGES - 1;
        if (tn < T) {
            const int nxt = tn & (GSTAGES - 1);
            cp16(&As[nxt][ar0 * ASTR + ac0], Ap0 + tn * 16);
            cp16(&As[nxt][ar1 * ASTR + ac1], Ap1 + tn * 16);
            cp16(&Bs[nxt][br0 * BSTR + bc0], Bp0 + (size_t)tn * 16 * N);
            cp16(&Bs[nxt][br1 * BSTR + bc1], Bp1 + (size_t)tn * 16 * N);
        }
        CP_COMMIT();
    }

    if (GELU_FUSE) {
        const int NO = N >> 1;
        #pragma unroll
        for (int nt = 0; nt < 8; nt++) {
            const int c = bn + wn * 64 + nt * 8 + tg * 2;
            const float2 bv = *(const float2*)(bias + c);
            const int j = c >> 1;
            #pragma unroll
            for (int mt = 0; mt < 2; mt++) {
                const int r0 = bm + wm * 32 + mt * 16 + g;
                if (r0 < M)
                    C[(size_t)r0 * NO + j] = (acc[mt][nt][0] + bv.x) * gelu_tanh(acc[mt][nt][1] + bv.y);
                const int r1 = r0 + 8;
                if (r1 < M)
                    C[(size_t)r1 * NO + j] = (acc[mt][nt][2] + bv.x) * gelu_tanh(acc[mt][nt][3] + bv.y);
            }
        }
    } else {
        #pragma unroll
        for (int nt = 0; nt < 8; nt++) {
            const int c = bn + wn * 64 + nt * 8 + tg * 2;
            float bx = 0.f, by = 0.f;
            if (bias) { const float2 bv = *(const float2*)(bias + c); bx = bv.x; by = bv.y; }
            #pragma unroll
            for (int mt = 0; mt < 2; mt++) {
                const int r0 = bm + wm * 32 + mt * 16 + g;
                if (r0 < M) {
                    float2 v = make_float2(acc[mt][nt][0] + bx, acc[mt][nt][1] + by);
                    if (resid) { const float2 rv = *(const float2*)(resid + (size_t)r0 * N + c); v.x += rv.x; v.y += rv.y; }
                    *(float2*)(C + (size_t)r0 * N + c) = v;
                }
                const int r1 = r0 + 8;
                if (r1 < M) {
                    float2 v = make_float2(acc[mt][nt][2] + bx, acc[mt][nt][3] + by);
                    if (resid) { const float2 rv = *(const float2*)(resid + (size_t)r1 * N + c); v.x += rv.x; v.y += rv.y; }
                    *(float2*)(C + (size_t)r1 * N + c) = v;
                }
            }
        }
    }
}

// ---------------- tf32 MMA flash attention: 64-q tile, 4 warps, Q in registers, 3 CTAs/SM ----------------
#define KSTR 72
#define VSTR 88
#define PSTR 76
#define KS_OFF 0
#define VS_OFF (80 * KSTR)                        // 5760
#define PS_OFF (VS_OFF + 64 * VSTR)               // 11392
#define ATTN_SMEM_FLOATS (PS_OFF + 64 * PSTR)     // 16256
#define ATTN_SMEM_BYTES  (ATTN_SMEM_FLOATS * 4)   // 65024

__global__ __launch_bounds__(128, 3) void attn_mma_kernel(
    const float* __restrict__ Q, const float* __restrict__ Kbuf,
    const float* __restrict__ Vbuf, float* __restrict__ O,
    const int* __restrict__ vlp, int kv_len, int mode, int kv_seq,
    int qld, int kvld)
{
    extern __shared__ float sm[];
    float* Ks = sm + KS_OFF;
    float* Vs = sm + VS_OFF;
    float* Ps = sm + PS_OFF;

    const int tid  = threadIdx.x;
    const int lane = tid & 31, warp = tid >> 5;   // 4 warps
    const int g = lane >> 2, tg = lane & 3;
    const int h  = blockIdx.y;
    const int bf = blockIdx.z;
    const int q0 = blockIdx.x * 64;

    int frame0_row0, prev_row0 = 0;
    if (mode == 0) {
        const int f = vlp[0];
        const int b_idx = bf / f;
        const int fr = bf - b_idx * f;
        const int pf = (fr == 0) ? 0 : (fr - 1);
        frame0_row0 = (b_idx * f) * kv_seq;
        prev_row0   = (b_idx * f + pf) * kv_seq;
    } else {
        frame0_row0 = bf * kv_seq;
    }

    // ---- load Q MMA fragments directly to registers (scaled, tf32) ----
    // thread owns rows r0 = q0 + warp*16 + g and r1 = r0 + 8; cols k8*8 + tg (+4)
    uint32_t qf[10][4];
    {
        const float* q0p = Q + ((size_t)bf * S_Q + q0 + warp * 16 + g) * qld + h * HD;
        const float* q1p = q0p + (size_t)8 * qld;
        #pragma unroll
        for (int k8 = 0; k8 < 10; k8++) {
            qf[k8][0] = __float_as_uint(to_tf32(q0p[k8 * 8 + tg]     * ATTN_SCALE));
            qf[k8][1] = __float_as_uint(to_tf32(q1p[k8 * 8 + tg]     * ATTN_SCALE));
            qf[k8][2] = __float_as_uint(to_tf32(q0p[k8 * 8 + tg + 4] * ATTN_SCALE));
            qf[k8][3] = __float_as_uint(to_tf32(q1p[k8 * 8 + tg + 4] * ATTN_SCALE));
        }
    }

    float o[10][4];
    #pragma unroll
    for (int nt = 0; nt < 10; nt++)
        #pragma unroll
        for (int i = 0; i < 4; i++) o[nt][i] = 0.f;
    float m0 = NEG_BIG, m1 = NEG_BIG, l0 = 0.f, l1 = 0.f;

    // KV producer: 128 threads = (key j = tid>>1, half = (tid&1)*40)
    const int kj = tid >> 1;
    const int kq = (tid & 1) * 40;

    const int ntiles = (kv_len + 63) >> 6;
    for (int t = 0; t < ntiles; t++) {
        const int kbase = t * 64;
        {
            const int jg = kbase + kj;
            const bool valid = jg < kv_len;
            int row = 0;
            if (valid) {
                if (mode == 0) row = (jg < kv_seq) ? (frame0_row0 + jg) : (prev_row0 + jg - kv_seq);
                else           row = frame0_row0 + jg;
            }
            const float* ksrc = Kbuf + (size_t)row * kvld + h * HD + kq;
            const float* vsrc = Vbuf + (size_t)row * kvld + h * HD + kq;
            float* vdst = Vs + kj * VSTR + kq;
            #pragma unroll
            for (int i = 0; i < 10; i++) {
                float4 kv = valid ? *(const float4*)(ksrc + i * 4) : make_float4(0.f,0.f,0.f,0.f);
                float4 vv = valid ? *(const float4*)(vsrc + i * 4) : make_float4(0.f,0.f,0.f,0.f);
                const int d = kq + i * 4;
                Ks[(d + 0) * KSTR + kj] = to_tf32(kv.x);
                Ks[(d + 1) * KSTR + kj] = to_tf32(kv.y);
                Ks[(d + 2) * KSTR + kj] = to_tf32(kv.z);
                Ks[(d + 3) * KSTR + kj] = to_tf32(kv.w);
                float4 vt = make_float4(to_tf32(vv.x), to_tf32(vv.y), to_tf32(vv.z), to_tf32(vv.w));
                *(float4*)(vdst + i * 4) = vt;
            }
        }
        __syncthreads();

        // ---- S = Q @ K^T ----
        float s[8][4];
        #pragma unroll
        for (int nt = 0; nt < 8; nt++)
            #pragma unroll
            for (int i = 0; i < 4; i++) s[nt][i] = 0.f;

        #pragma unroll
        for (int k8 = 0; k8 < 10; k8++) {
            uint32_t bfg[8][2];
            #pragma unroll
            for (int nt = 0; nt < 8; nt++) {
                const float* bp = Ks + (k8 * 8 + tg) * KSTR + nt * 8 + g;
                bfg[nt][0] = __float_as_uint(bp[0]);
                bfg[nt][1] = __float_as_uint(bp[4 * KSTR]);
            }
            #pragma unroll
            for (int nt = 0; nt < 8; nt++) mma_tf32(s[nt], qf[k8], bfg[nt]);
        }

        float mx0 = NEG_BIG, mx1 = NEG_BIG;
        #pragma unroll
        for (int nt = 0; nt < 8; nt++) {
            if (mode == 1) {
                const int c0 = kbase + nt * 8 + 2 * tg;
                if (c0 >= kv_len)     { s[nt][0] = NEG_BIG; s[nt][2] = NEG_BIG; }
                if (c0 + 1 >= kv_len) { s[nt][1] = NEG_BIG; s[nt][3] = NEG_BIG; }
            }
            mx0 = fmaxf(mx0, fmaxf(s[nt][0], s[nt][1]));
            mx1 = fmaxf(mx1, fmaxf(s[nt][2], s[nt][3]));
        }
        mx0 = fmaxf(mx0, __shfl_xor_sync(0xFFFFFFFFu, mx0, 1));
        mx0 = fmaxf(mx0, __shfl_xor_sync(0xFFFFFFFFu, mx0, 2));
        mx1 = fmaxf(mx1, __shfl_xor_sync(0xFFFFFFFFu, mx1, 1));
        mx1 = fmaxf(mx1, __shfl_xor_sync(0xFFFFFFFFu, mx1, 2));

        const float mn0 = fmaxf(m0, mx0), mn1 = fmaxf(m1, mx1);
        const float a0 = __expf(m0 - mn0), a1 = __expf(m1 - mn1);
        l0 *= a0; l1 *= a1;
        #pragma unroll
        for (int nt = 0; nt < 10; nt++) {
            o[nt][0] *= a0; o[nt][1] *= a0; o[nt][2] *= a1; o[nt][3] *= a1;
        }

        float ls0 = 0.f, ls1 = 0.f;
        {
            float* pr0 = Ps + (warp * 16 + g) * PSTR + 2 * tg;
            float* pr1 = pr0 + 8 * PSTR;
            #pragma unroll
            for (int nt = 0; nt < 8; nt++) {
                const float p0 = __expf(s[nt][0] - mn0);
                const float p1 = __expf(s[nt][1] - mn0);
                const float p2 = __expf(s[nt][2] - mn1);
                const float p3 = __expf(s[nt][3] - mn1);
                ls0 += p0 + p1; ls1 += p2 + p3;
                *(float2*)(pr0 + nt * 8) = make_float2(to_tf32(p0), to_tf32(p1));
                *(float2*)(pr1 + nt * 8) = make_float2(to_tf32(p2), to_tf32(p3));
            }
        }
        ls0 += __shfl_xor_sync(0xFFFFFFFFu, ls0, 1);
        ls0 += __shfl_xor_sync(0xFFFFFFFFu, ls0, 2);
        ls1 += __shfl_xor_sync(0xFFFFFFFFu, ls1, 1);
        ls1 += __shfl_xor_sync(0xFFFFFFFFu, ls1, 2);
        l0 += ls0; l1 += ls1;
        m0 = mn0; m1 = mn1;
        __syncwarp();

        // ---- O += P @ V ----
        #pragma unroll
        for (int k8 = 0; k8 < 8; k8++) {
            uint32_t af[4], bfg[10][2];
            const float* ap = Ps + (warp * 16 + g) * PSTR + k8 * 8 + tg;
            af[0] = __float_as_uint(ap[0]);
            af[1] = __float_as_uint(ap[8 * PSTR]);
            af[2] = __float_as_uint(ap[4]);
            af[3] = __float_as_uint(ap[8 * PSTR + 4]);
            #pragma unroll
            for (int nt = 0; nt < 10; nt++) {
                const float* bp = Vs + (k8 * 8 + tg) * VSTR + nt * 8 + g;
                bfg[nt][0] = __float_as_uint(bp[0]);
                bfg[nt][1] = __float_as_uint(bp[4 * VSTR]);
            }
            #pragma unroll
            for (int nt = 0; nt < 10; nt++) mma_tf32(o[nt], af, bfg[nt]);
        }
        __syncthreads();
    }

    const float inv0 = 1.0f / l0, inv1 = 1.0f / l1;
    const size_t r0 = (size_t)bf * S_Q + q0 + warp * 16 + g;
    const size_t r1 = r0 + 8;
    float* o0 = O + r0 * D_MODEL + h * HD + 2 * tg;
    float* o1 = O + r1 * D_MODEL + h * HD + 2 * tg;
    #pragma unroll
    for (int nt = 0; nt < 10; nt++) {
        *(float2*)(o0 + nt * 8) = make_float2(o[nt][0] * inv0, o[nt][1] * inv0);
        *(float2*)(o1 + nt * 8) = make_float2(o[nt][2] * inv1, o[nt][3] * inv1);
    }
}

// ---------------- host ----------------
static inline void run_gemm_s(cudaStream_t st, const float* A, const float* B, const float* bias,
                              const float* resid, float* C, int M, int N, int K) {
    dim3 grid(N / 128, (M + 127) / 128);
    gemm_tf32_kernel_t<0><<<grid, 256, 0, st>>>(A, B, bias, resid, C, M, N, K);
}
static inline void run_gemm(const float* A, const float* B, const float* bias,
                            const float* resid, float* C, int M, int N, int K) {
    run_gemm_s(0, A, B, bias, resid, C, M, N, K);
}
static inline void run_gemm_gelu(const float* A, const float* B, const float* bias,
                                 float* C, int M, int N, int K) {
    dim3 grid(N / 128, (M + 127) / 128);
    gemm_tf32_kernel_t<1><<<grid, 256>>>(A, B, bias, nullptr, C, M, N, K);
}
static inline void run_ln(const float* x, const float* w, const float* b,
                          float* out, int rows) {
    ln_kernel<<<(rows + 7) / 8, 256>>>(x, w, b, out, rows);
}

extern "C" void kernel_launch(void* const* d_in, const int* in_sizes, int n_in,
                              void* d_out, int out_size) {
    const float* hidden = (const float*)d_in[0];
    const float* enc    = (const float*)d_in[1];
    const int*   vl     = (const int*)d_in[2];
    const float* ln1_w  = (const float*)d_in[3];
    const float* ln1_b  = (const float*)d_in[4];
    const float* q1     = (const float*)d_in[5];
    const float* k1     = (const float*)d_in[6];
    const float* v1     = (const float*)d_in[7];
    const float* o1_w   = (const float*)d_in[8];
    const float* o1_b   = (const float*)d_in[9];
    const float* ln2_w  = (const float*)d_in[10];
    const float* ln2_b  = (const float*)d_in[11];
    const float* q2     = (const float*)d_in[12];
    const float* k2     = (const float*)d_in[13];
    const float* v2     = (const float*)d_in[14];
    const float* o2_w   = (const float*)d_in[15];
    const float* o2_b   = (const float*)d_in[16];
    const float* ln3_w  = (const float*)d_in[17];
    const float* ln3_b  = (const float*)d_in[18];
    const float* ff_w1  = (const float*)d_in[19];
    const float* ff_b1  = (const float*)d_in[20];
    const float* ff_w2  = (const float*)d_in[21];
    const float* ff_b2  = (const float*)d_in[22];
    float* out = (float*)d_out;

    const int BF   = in_sizes[0] / (S_Q * D_MODEL);          // 8
    const int ROWS = BF * S_Q;                               // 8192
    const int EB   = in_sizes[1] / (ENC_LEN * ENC_DIM);      // 8
    const int EROWS = EB * ENC_LEN;                          // 616

    static int init_done = 0;
    static cudaStream_t s_side = nullptr;
    static cudaEvent_t evRoot = nullptr, evPack = nullptr, evKV = nullptr;
    if (!init_done) {
        cudaFuncSetAttribute(attn_mma_kernel, cudaFuncAttributeMaxDynamicSharedMemorySize, ATTN_SMEM_BYTES);
        cudaStreamCreateWithFlags(&s_side, cudaStreamNonBlocking);
        cudaEventCreateWithFlags(&evRoot, cudaEventDisableTiming);
        cudaEventCreateWithFlags(&evPack, cudaEventDisableTiming);
        cudaEventCreateWithFlags(&evKV,   cudaEventDisableTiming);
        init_done = 1;
    }

    float *x, *qkv, *q2b, *kvb, *ab, *h2, *h3, *gated, *wqkv, *wkv, *w1p, *b1p;
    cudaGetSymbolAddress((void**)&x,    g_x);
    cudaGetSymbolAddress((void**)&qkv,  g_qkv);
    cudaGetSymbolAddress((void**)&q2b,  g_q2);
    cudaGetSymbolAddress((void**)&kvb,  g_kv);
    cudaGetSymbolAddress((void**)&ab,   g_attn);
    cudaGetSymbolAddress((void**)&h2,   g_h2);
    cudaGetSymbolAddress((void**)&h3,   g_h3);
    cudaGetSymbolAddress((void**)&gated, g_gated);
    cudaGetSymbolAddress((void**)&wqkv, g_wqkv);
    cudaGetSymbolAddress((void**)&wkv,  g_wkv);
    cudaGetSymbolAddress((void**)&w1p,  g_w1p);
    cudaGetSymbolAddress((void**)&b1p,  g_b1p);

    // ---- fork: side stream does packs + kv2 GEMM; main does ln1 ----
    cudaEventRecord(evRoot, 0);
    cudaStreamWaitEvent(s_side, evRoot, 0);
    {
        const int n3 = D_MODEL * D_MODEL;
        pack3_kernel<<<(n3 + 255) / 256, 256, 0, s_side>>>(q1, k1, v1, wqkv, D_MODEL, D_MODEL);
        const int n2 = ENC_DIM * D_MODEL;
        pack2_kernel<<<(n2 + 255) / 256, 256, 0, s_side>>>(k2, v2, wkv, ENC_DIM, D_MODEL);
        const int nw1 = D_MODEL * PROJ_N;
        packw1_kernel<<<(nw1 + 255) / 256, 256, 0, s_side>>>(ff_w1, w1p, ff_b1, b1p);
    }
    cudaEventRecord(evPack, s_side);
    run_gemm_s(s_side, enc, wkv, nullptr, nullptr, kvb, EROWS, 2 * D_MODEL, ENC_DIM);
    cudaEventRecord(evKV, s_side);

    // ---- block 1: self-attn with temporal KV gather ----
    run_ln(hidden, ln1_w, ln1_b, x, ROWS);
    cudaStreamWaitEvent(0, evPack, 0);
    run_gemm(x, wqkv, nullptr, nullptr, qkv, ROWS, 3 * D_MODEL, D_MODEL);
    {
        dim3 grid(S_Q / 64, N_HEADS, BF);
        attn_mma_kernel<<<grid, 128, ATTN_SMEM_BYTES>>>(
            qkv, qkv + D_MODEL, qkv + 2 * D_MODEL, ab, vl,
            2 * S_Q, 0, S_Q, 3 * D_MODEL, 3 * D_MODEL);
    }
    run_gemm(ab, o1_w, o1_b, hidden, h2, ROWS, D_MODEL, D_MODEL);

    // ---- block 2: cross attention ----
    run_ln(h2, ln2_w, ln2_b, x, ROWS);
    run_gemm(x, q2, nullptr, nullptr, q2b, ROWS, D_MODEL, D_MODEL);
    cudaStreamWaitEvent(0, evKV, 0);
    {
        dim3 grid(S_Q / 64, N_HEADS, BF);
        attn_mma_kernel<<<grid, 128, ATTN_SMEM_BYTES>>>(
            q2b, kvb, kvb + D_MODEL, ab, vl,
            ENC_LEN, 1, ENC_LEN, D_MODEL, 2 * D_MODEL);
    }
    run_gemm(ab, o2_w, o2_b, h2, h3, ROWS, D_MODEL, D_MODEL);

    // ---- block 3: fused gated-GeLU FF ----
    run_ln(h3, ln3_w, ln3_b, x, ROWS);
    run_gemm_gelu(x, w1p, b1p, gated, ROWS, PROJ_N, D_MODEL);
    run_gemm(gated, ff_w2, ff_b2, h3, out, ROWS, D_MODEL, FF_IN);
}

// round 16
// speedup vs baseline: 1.3996x; 1.2924x over previous
#include <cuda_runtime.h>
#include <cuda_bf16.h>
#include <cuda_fp16.h>
#include <math.h>
#include <stdint.h>

// ---------------- problem constants ----------------
#define S_Q      1024
#define D_MODEL  640
#define N_HEADS  8
#define HD       80
#define ENC_LEN  77
#define ENC_DIM  768
#define FF_IN    2560
#define PROJ_N   5120
#define BF_MAX   8
#define ROWS_MAX (BF_MAX * S_Q)
#define ATTN_SCALE 0.11180339887498949f
#define NEG_BIG  -3.0e38f

// ---------------- scratch ----------------
__device__ __half g_xh[ROWS_MAX * D_MODEL];            // LN outputs (half)
__device__ __half g_abh[ROWS_MAX * D_MODEL];           // attention outputs (half)
__device__ __half g_gatedh[ROWS_MAX * FF_IN];          // gated-gelu (half)
__device__ __half g_ench[1024 * ENC_DIM];              // enc converted
__device__ float  g_qkv[ROWS_MAX * 3 * D_MODEL];
__device__ float  g_q2[ROWS_MAX * D_MODEL];
__device__ float  g_kv[1024 * 2 * D_MODEL];
__device__ float  g_h2[ROWS_MAX * D_MODEL];
__device__ float  g_h3[ROWS_MAX * D_MODEL];
// transposed half weights [N][K]
__device__ __half g_wqkvh[3 * D_MODEL * D_MODEL];
__device__ __half g_o1h[D_MODEL * D_MODEL];
__device__ __half g_q2h[D_MODEL * D_MODEL];
__device__ __half g_o2h[D_MODEL * D_MODEL];
__device__ __half g_wkvh[2 * D_MODEL * ENC_DIM];
__device__ __half g_w1ph[PROJ_N * D_MODEL];            // interleaved (h,gate) rows, transposed
__device__ __half g_w2h[D_MODEL * FF_IN];
__device__ float  g_b1p[PROJ_N];

// ---------------- helpers ----------------
__device__ __forceinline__ float to_tf32(float x) {
    uint32_t r;
    asm("cvt.rna.tf32.f32 %0, %1;" : "=r"(r) : "f"(x));
    return __uint_as_float(r);
}
__device__ __forceinline__ void mma_tf32(float c[4], const uint32_t a[4], const uint32_t b[2]) {
    asm volatile(
        "mma.sync.aligned.m16n8k8.row.col.f32.tf32.tf32.f32 "
        "{%0,%1,%2,%3}, {%4,%5,%6,%7}, {%8,%9}, {%0,%1,%2,%3};"
        : "+f"(c[0]), "+f"(c[1]), "+f"(c[2]), "+f"(c[3])
        : "r"(a[0]), "r"(a[1]), "r"(a[2]), "r"(a[3]), "r"(b[0]), "r"(b[1]));
}
__device__ __forceinline__ void mma_f16(float c[4], const uint32_t a[4], const uint32_t b[2]) {
    asm volatile(
        "mma.sync.aligned.m16n8k16.row.col.f32.f16.f16.f32 "
        "{%0,%1,%2,%3}, {%4,%5,%6,%7}, {%8,%9}, {%0,%1,%2,%3};"
        : "+f"(c[0]), "+f"(c[1]), "+f"(c[2]), "+f"(c[3])
        : "r"(a[0]), "r"(a[1]), "r"(a[2]), "r"(a[3]), "r"(b[0]), "r"(b[1]));
}
__device__ __forceinline__ void cp16(void* smem, const void* gmem) {
    uint32_t a = (uint32_t)__cvta_generic_to_shared(smem);
    asm volatile("cp.async.cg.shared.global [%0], [%1], 16;" :: "r"(a), "l"(gmem));
}
#define CP_COMMIT() asm volatile("cp.async.commit_group;")
#define CP_WAIT2()  asm volatile("cp.async.wait_group 2;")

__device__ __forceinline__ float gelu_tanh(float g) {
    const float u = 0.7978845608028654f * (g + 0.044715f * g * g * g);
    return g * __frcp_rn(1.0f + __expf(-2.0f * u));
}

// ---------------- weight packing (all on side stream) ----------------
// transpose + convert: src [K][N] fp32 row-major -> dst [N][K] half
__global__ void tcvt_kernel(const float* __restrict__ src, __half* __restrict__ dst,
                            int K, int N) {
    const int idx = blockIdx.x * blockDim.x + threadIdx.x;
    if (idx >= N * K) return;
    const int n = idx / K, k = idx - n * K;
    dst[idx] = __float2half(src[(size_t)k * N + n]);
}
// ff_w1 -> interleaved transposed half: dst[(2j+s)*K + k] = w[k][s*FF_IN + j]
__global__ void w1t_kernel(const float* __restrict__ w, __half* __restrict__ dst,
                           const float* __restrict__ b, float* __restrict__ bout) {
    const int idx = blockIdx.x * blockDim.x + threadIdx.x;
    if (idx < PROJ_N) {
        const int jb = idx >> 1, sb = idx & 1;
        bout[idx] = b[sb * FF_IN + jb];
    }
    if (idx >= PROJ_N * D_MODEL) return;
    const int n = idx / D_MODEL, k = idx - n * D_MODEL;
    const int j = n >> 1, s = n & 1;
    dst[idx] = __float2half(w[(size_t)k * PROJ_N + s * FF_IN + j]);
}
// plain convert
__global__ void cvt_kernel(const float* __restrict__ src, __half* __restrict__ dst, int n) {
    const int idx = blockIdx.x * blockDim.x + threadIdx.x;
    if (idx < n) dst[idx] = __float2half(src[idx]);
}

// ---------------- LayerNorm: warp-per-row, half output ----------------
__global__ __launch_bounds__(256) void ln_kernel(
    const float* __restrict__ x, const float* __restrict__ w,
    const float* __restrict__ b, __half* __restrict__ out, int rows) {
    const int warp = threadIdx.x >> 5, lane = threadIdx.x & 31;
    const int row = blockIdx.x * 8 + warp;
    if (row >= rows) return;
    const float* xr = x + (size_t)row * D_MODEL;
    __half* orow = out + (size_t)row * D_MODEL;

    float4 v[5];
    float s = 0.f, s2 = 0.f;
    #pragma unroll
    for (int i = 0; i < 5; i++) {
        v[i] = *(const float4*)(xr + i * 128 + lane * 4);
        s  += v[i].x + v[i].y + v[i].z + v[i].w;
        s2 += v[i].x * v[i].x + v[i].y * v[i].y + v[i].z * v[i].z + v[i].w * v[i].w;
    }
    #pragma unroll
    for (int o = 16; o; o >>= 1) {
        s  += __shfl_xor_sync(0xFFFFFFFFu, s,  o);
        s2 += __shfl_xor_sync(0xFFFFFFFFu, s2, o);
    }
    const float mean = s * (1.0f / D_MODEL);
    const float var  = s2 * (1.0f / D_MODEL) - mean * mean;
    const float rstd = rsqrtf(var + 1e-5f);
    #pragma unroll
    for (int i = 0; i < 5; i++) {
        const int c = i * 128 + lane * 4;
        const float4 wv = *(const float4*)(w + c);
        const float4 bv = *(const float4*)(b + c);
        *(half2*)(orow + c)     = __floats2half2_rn((v[i].x - mean) * rstd * wv.x + bv.x,
                                                    (v[i].y - mean) * rstd * wv.y + bv.y);
        *(half2*)(orow + c + 2) = __floats2half2_rn((v[i].z - mean) * rstd * wv.z + bv.z,
                                                    (v[i].w - mean) * rstd * wv.w + bv.w);
    }
}

// ---------------- fp16 GEMM: 128x128 block, 8 warps, warp 32x64, BK16, 4-stage ----------------
// A [M][K] half row-major, B' [N][K] half (pre-transposed). C fp32 (or half when GELU_FUSE).
#define AHALF 24      // halves per smem row (12 words; 12 mod 32 -> conflict-free frags)
#define GSTAGES 4

template<int GELU_FUSE>
__global__ __launch_bounds__(256, 2) void gemm_f16_kernel_t(
    const __half* __restrict__ A, const __half* __restrict__ B,
    const float* __restrict__ bias, const float* __restrict__ resid,
    float* __restrict__ C, __half* __restrict__ Ch, int M, int N, int K)
{
    __shared__ __half As[GSTAGES][128 * AHALF];
    __shared__ __half Bs[GSTAGES][128 * AHALF];

    const int tid  = threadIdx.x;
    const int lane = tid & 31, warp = tid >> 5;
    const int wm = warp & 3, wn = warp >> 2;
    const int g  = lane >> 2, tg = lane & 3;
    const int bm = blockIdx.y * 128, bn = blockIdx.x * 128;

    const int prow = tid >> 1;              // 0..127
    const int pk   = (tid & 1) * 8;         // 0 or 8 halves
    const __half* Ap = A + (size_t)min(bm + prow, M - 1) * K + pk;
    const __half* Bp = B + (size_t)(bn + prow) * K + pk;

    float acc[2][8][4];
    #pragma unroll
    for (int mt = 0; mt < 2; mt++)
        #pragma unroll
        for (int nt = 0; nt < 8; nt++)
            #pragma unroll
            for (int i = 0; i < 4; i++) acc[mt][nt][i] = 0.f;

    const int T = K >> 4;

    #pragma unroll
    for (int s = 0; s < GSTAGES - 1; s++) {
        if (s < T) {
            cp16(&As[s][prow * AHALF + pk], Ap + s * 16);
            cp16(&Bs[s][prow * AHALF + pk], Bp + s * 16);
        }
        CP_COMMIT();
    }

    for (int t = 0; t < T; t++) {
        CP_WAIT2();
        __syncthreads();

        const int cur = t & (GSTAGES - 1);
        const __half* as = As[cur];
        const __half* bs = Bs[cur];
        uint32_t af[2][4], bf[8][2];
        #pragma unroll
        for (int mt = 0; mt < 2; mt++) {
            const int r = wm * 32 + mt * 16 + g;
            af[mt][0] = *(const uint32_t*)(as + r * AHALF + 2 * tg);
            af[mt][1] = *(const uint32_t*)(as + (r + 8) * AHALF + 2 * tg);
            af[mt][2] = *(const uint32_t*)(as + r * AHALF + 2 * tg + 8);
            af[mt][3] = *(const uint32_t*)(as + (r + 8) * AHALF + 2 * tg + 8);
        }
        #pragma unroll
        for (int nt = 0; nt < 8; nt++) {
            const int rn = wn * 64 + nt * 8 + g;
            bf[nt][0] = *(const uint32_t*)(bs + rn * AHALF + 2 * tg);
            bf[nt][1] = *(const uint32_t*)(bs + rn * AHALF + 2 * tg + 8);
        }
        #pragma unroll
        for (int mt = 0; mt < 2; mt++)
            #pragma unroll
            for (int nt = 0; nt < 8; nt++)
                mma_f16(acc[mt][nt], af[mt], bf[nt]);

        const int tn = t + GSTAGES - 1;
        if (tn < T) {
            const int nxt = tn & (GSTAGES - 1);
            cp16(&As[nxt][prow * AHALF + pk], Ap + tn * 16);
            cp16(&Bs[nxt][prow * AHALF + pk], Bp + tn * 16);
        }
        CP_COMMIT();
    }

    if (GELU_FUSE) {
        const int NO = N >> 1;
        #pragma unroll
        for (int nt = 0; nt < 8; nt++) {
            const int c = bn + wn * 64 + nt * 8 + tg * 2;
            const float2 bv = *(const float2*)(bias + c);
            const int j = c >> 1;
            #pragma unroll
            for (int mt = 0; mt < 2; mt++) {
                const int r0 = bm + wm * 32 + mt * 16 + g;
                if (r0 < M)
                    Ch[(size_t)r0 * NO + j] = __float2half((acc[mt][nt][0] + bv.x) * gelu_tanh(acc[mt][nt][1] + bv.y));
                const int r1 = r0 + 8;
                if (r1 < M)
                    Ch[(size_t)r1 * NO + j] = __float2half((acc[mt][nt][2] + bv.x) * gelu_tanh(acc[mt][nt][3] + bv.y));
            }
        }
    } else {
        #pragma unroll
        for (int nt = 0; nt < 8; nt++) {
            const int c = bn + wn * 64 + nt * 8 + tg * 2;
            float bx = 0.f, by = 0.f;
            if (bias) { const float2 bv = *(const float2*)(bias + c); bx = bv.x; by = bv.y; }
            #pragma unroll
            for (int mt = 0; mt < 2; mt++) {
                const int r0 = bm + wm * 32 + mt * 16 + g;
                if (r0 < M) {
                    float2 v = make_float2(acc[mt][nt][0] + bx, acc[mt][nt][1] + by);
                    if (resid) { const float2 rv = *(const float2*)(resid + (size_t)r0 * N + c); v.x += rv.x; v.y += rv.y; }
                    *(float2*)(C + (size_t)r0 * N + c) = v;
                }
                const int r1 = r0 + 8;
                if (r1 < M) {
                    float2 v = make_float2(acc[mt][nt][2] + bx, acc[mt][nt][3] + by);
                    if (resid) { const float2 rv = *(const float2*)(resid + (size_t)r1 * N + c); v.x += rv.x; v.y += rv.y; }
                    *(float2*)(C + (size_t)r1 * N + c) = v;
                }
            }
        }
    }
}

// ---------------- tf32 MMA flash attention: 64-q tile, 4 warps, Q in regs, half output ----------------
#define KSTR 72
#define VSTR 88
#define PSTR 76
#define KS_OFF 0
#define VS_OFF (80 * KSTR)
#define PS_OFF (VS_OFF + 64 * VSTR)
#define ATTN_SMEM_FLOATS (PS_OFF + 64 * PSTR)
#define ATTN_SMEM_BYTES  (ATTN_SMEM_FLOATS * 4)

__global__ __launch_bounds__(128, 3) void attn_mma_kernel(
    const float* __restrict__ Q, const float* __restrict__ Kbuf,
    const float* __restrict__ Vbuf, __half* __restrict__ O,
    const int* __restrict__ vlp, int kv_len, int mode, int kv_seq,
    int qld, int kvld)
{
    extern __shared__ float sm[];
    float* Ks = sm + KS_OFF;
    float* Vs = sm + VS_OFF;
    float* Ps = sm + PS_OFF;

    const int tid  = threadIdx.x;
    const int lane = tid & 31, warp = tid >> 5;
    const int g = lane >> 2, tg = lane & 3;
    const int h  = blockIdx.y;
    const int bf = blockIdx.z;
    const int q0 = blockIdx.x * 64;

    int frame0_row0, prev_row0 = 0;
    if (mode == 0) {
        const int f = vlp[0];
        const int b_idx = bf / f;
        const int fr = bf - b_idx * f;
        const int pf = (fr == 0) ? 0 : (fr - 1);
        frame0_row0 = (b_idx * f) * kv_seq;
        prev_row0   = (b_idx * f + pf) * kv_seq;
    } else {
        frame0_row0 = bf * kv_seq;
    }

    uint32_t qf[10][4];
    {
        const float* q0p = Q + ((size_t)bf * S_Q + q0 + warp * 16 + g) * qld + h * HD;
        const float* q1p = q0p + (size_t)8 * qld;
        #pragma unroll
        for (int k8 = 0; k8 < 10; k8++) {
            qf[k8][0] = __float_as_uint(to_tf32(q0p[k8 * 8 + tg]     * ATTN_SCALE));
            qf[k8][1] = __float_as_uint(to_tf32(q1p[k8 * 8 + tg]     * ATTN_SCALE));
            qf[k8][2] = __float_as_uint(to_tf32(q0p[k8 * 8 + tg + 4] * ATTN_SCALE));
            qf[k8][3] = __float_as_uint(to_tf32(q1p[k8 * 8 + tg + 4] * ATTN_SCALE));
        }
    }

    float o[10][4];
    #pragma unroll
    for (int nt = 0; nt < 10; nt++)
        #pragma unroll
        for (int i = 0; i < 4; i++) o[nt][i] = 0.f;
    float m0 = NEG_BIG, m1 = NEG_BIG, l0 = 0.f, l1 = 0.f;

    const int kj = tid >> 1;
    const int kq = (tid & 1) * 40;

    const int ntiles = (kv_len + 63) >> 6;
    for (int t = 0; t < ntiles; t++) {
        const int kbase = t * 64;
        {
            const int jg = kbase + kj;
            const bool valid = jg < kv_len;
            int row = 0;
            if (valid) {
                if (mode == 0) row = (jg < kv_seq) ? (frame0_row0 + jg) : (prev_row0 + jg - kv_seq);
                else           row = frame0_row0 + jg;
            }
            const float* ksrc = Kbuf + (size_t)row * kvld + h * HD + kq;
            const float* vsrc = Vbuf + (size_t)row * kvld + h * HD + kq;
            float* vdst = Vs + kj * VSTR + kq;
            #pragma unroll
            for (int i = 0; i < 10; i++) {
                float4 kv = valid ? *(const float4*)(ksrc + i * 4) : make_float4(0.f,0.f,0.f,0.f);
                float4 vv = valid ? *(const float4*)(vsrc + i * 4) : make_float4(0.f,0.f,0.f,0.f);
                const int d = kq + i * 4;
                Ks[(d + 0) * KSTR + kj] = to_tf32(kv.x);
                Ks[(d + 1) * KSTR + kj] = to_tf32(kv.y);
                Ks[(d + 2) * KSTR + kj] = to_tf32(kv.z);
                Ks[(d + 3) * KSTR + kj] = to_tf32(kv.w);
                float4 vt = make_float4(to_tf32(vv.x), to_tf32(vv.y), to_tf32(vv.z), to_tf32(vv.w));
                *(float4*)(vdst + i * 4) = vt;
            }
        }
        __syncthreads();

        float s[8][4];
        #pragma unroll
        for (int nt = 0; nt < 8; nt++)
            #pragma unroll
            for (int i = 0; i < 4; i++) s[nt][i] = 0.f;

        #pragma unroll
        for (int k8 = 0; k8 < 10; k8++) {
            uint32_t bfg[8][2];
            #pragma unroll
            for (int nt = 0; nt < 8; nt++) {
                const float* bp = Ks + (k8 * 8 + tg) * KSTR + nt * 8 + g;
                bfg[nt][0] = __float_as_uint(bp[0]);
                bfg[nt][1] = __float_as_uint(bp[4 * KSTR]);
            }
            #pragma unroll
            for (int nt = 0; nt < 8; nt++) mma_tf32(s[nt], qf[k8], bfg[nt]);
        }

        float mx0 = NEG_BIG, mx1 = NEG_BIG;
        #pragma unroll
        for (int nt = 0; nt < 8; nt++) {
            if (mode == 1) {
                const int c0 = kbase + nt * 8 + 2 * tg;
                if (c0 >= kv_len)     { s[nt][0] = NEG_BIG; s[nt][2] = NEG_BIG; }
                if (c0 + 1 >= kv_len) { s[nt][1] = NEG_BIG; s[nt][3] = NEG_BIG; }
            }
            mx0 = fmaxf(mx0, fmaxf(s[nt][0], s[nt][1]));
            mx1 = fmaxf(mx1, fmaxf(s[nt][2], s[nt][3]));
        }
        mx0 = fmaxf(mx0, __shfl_xor_sync(0xFFFFFFFFu, mx0, 1));
        mx0 = fmaxf(mx0, __shfl_xor_sync(0xFFFFFFFFu, mx0, 2));
        mx1 = fmaxf(mx1, __shfl_xor_sync(0xFFFFFFFFu, mx1, 1));
        mx1 = fmaxf(mx1, __shfl_xor_sync(0xFFFFFFFFu, mx1, 2));

        const float mn0 = fmaxf(m0, mx0), mn1 = fmaxf(m1, mx1);
        const float a0 = __expf(m0 - mn0), a1 = __expf(m1 - mn1);
        l0 *= a0; l1 *= a1;
        #pragma unroll
        for (int nt = 0; nt < 10; nt++) {
            o[nt][0] *= a0; o[nt][1] *= a0; o[nt][2] *= a1; o[nt][3] *= a1;
        }

        float ls0 = 0.f, ls1 = 0.f;
        {
            float* pr0 = Ps + (warp * 16 + g) * PSTR + 2 * tg;
            float* pr1 = pr0 + 8 * PSTR;
            #pragma unroll
            for (int nt = 0; nt < 8; nt++) {
                const float p0 = __expf(s[nt][0] - mn0);
                const float p1 = __expf(s[nt][1] - mn0);
                const float p2 = __expf(s[nt][2] - mn1);
                const float p3 = __expf(s[nt][3] - mn1);
                ls0 += p0 + p1; ls1 += p2 + p3;
                *(float2*)(pr0 + nt * 8) = make_float2(to_tf32(p0), to_tf32(p1));
                *(float2*)(pr1 + nt * 8) = make_float2(to_tf32(p2), to_tf32(p3));
            }
        }
        ls0 += __shfl_xor_sync(0xFFFFFFFFu, ls0, 1);
        ls0 += __shfl_xor_sync(0xFFFFFFFFu, ls0, 2);
        ls1 += __shfl_xor_sync(0xFFFFFFFFu, ls1, 1);
        ls1 += __shfl_xor_sync(0xFFFFFFFFu, ls1, 2);
        l0 += ls0; l1 += ls1;
        m0 = mn0; m1 = mn1;
        __syncwarp();

        #pragma unroll
        for (int k8 = 0; k8 < 8; k8++) {
            uint32_t af[4], bfg[10][2];
            const float* ap = Ps + (warp * 16 + g) * PSTR + k8 * 8 + tg;
            af[0] = __float_as_uint(ap[0]);
            af[1] = __float_as_uint(ap[8 * PSTR]);
            af[2] = __float_as_uint(ap[4]);
            af[3] = __float_as_uint(ap[8 * PSTR + 4]);
            #pragma unroll
            for (int nt = 0; nt < 10; nt++) {
                const float* bp = Vs + (k8 * 8 + tg) * VSTR + nt * 8 + g;
                bfg[nt][0] = __float_as_uint(bp[0]);
                bfg[nt][1] = __float_as_uint(bp[4 * VSTR]);
            }
            #pragma unroll
            for (int nt = 0; nt < 10; nt++) mma_tf32(o[nt], af, bfg[nt]);
        }
        __syncthreads();
    }

    const float inv0 = 1.0f / l0, inv1 = 1.0f / l1;
    const size_t r0 = (size_t)bf * S_Q + q0 + warp * 16 + g;
    const size_t r1 = r0 + 8;
    __half* o0 = O + r0 * D_MODEL + h * HD + 2 * tg;
    __half* o1 = O + r1 * D_MODEL + h * HD + 2 * tg;
    #pragma unroll
    for (int nt = 0; nt < 10; nt++) {
        *(half2*)(o0 + nt * 8) = __floats2half2_rn(o[nt][0] * inv0, o[nt][1] * inv0);
        *(half2*)(o1 + nt * 8) = __floats2half2_rn(o[nt][2] * inv1, o[nt][3] * inv1);
    }
}

// ---------------- host ----------------
static inline void run_gemm_s(cudaStream_t st, const __half* A, const __half* B,
                              const float* bias, const float* resid, float* C,
                              int M, int N, int K) {
    dim3 grid(N / 128, (M + 127) / 128);
    gemm_f16_kernel_t<0><<<grid, 256, 0, st>>>(A, B, bias, resid, C, nullptr, M, N, K);
}
static inline void run_gemm(const __half* A, const __half* B, const float* bias,
                            const float* resid, float* C, int M, int N, int K) {
    run_gemm_s(0, A, B, bias, resid, C, M, N, K);
}
static inline void run_gemm_gelu(const __half* A, const __half* B, const float* bias,
                                 __half* Ch, int M, int N, int K) {
    dim3 grid(N / 128, (M + 127) / 128);
    gemm_f16_kernel_t<1><<<grid, 256>>>(A, B, bias, nullptr, nullptr, Ch, M, N, K);
}
static inline void run_ln(const float* x, const float* w, const float* b,
                          __half* out, int rows) {
    ln_kernel<<<(rows + 7) / 8, 256>>>(x, w, b, out, rows);
}
static inline void run_tcvt(cudaStream_t st, const float* src, __half* dst, int K, int N) {
    const int n = N * K;
    tcvt_kernel<<<(n + 255) / 256, 256, 0, st>>>(src, dst, K, N);
}

extern "C" void kernel_launch(void* const* d_in, const int* in_sizes, int n_in,
                              void* d_out, int out_size) {
    const float* hidden = (const float*)d_in[0];
    const float* enc    = (const float*)d_in[1];
    const int*   vl     = (const int*)d_in[2];
    const float* ln1_w  = (const float*)d_in[3];
    const float* ln1_b  = (const float*)d_in[4];
    const float* q1     = (const float*)d_in[5];
    const float* k1     = (const float*)d_in[6];
    const float* v1     = (const float*)d_in[7];
    const float* o1_w   = (const float*)d_in[8];
    const float* o1_b   = (const float*)d_in[9];
    const float* ln2_w  = (const float*)d_in[10];
    const float* ln2_b  = (const float*)d_in[11];
    const float* q2     = (const float*)d_in[12];
    const float* k2     = (const float*)d_in[13];
    const float* v2     = (const float*)d_in[14];
    const float* o2_w   = (const float*)d_in[15];
    const float* o2_b   = (const float*)d_in[16];
    const float* ln3_w  = (const float*)d_in[17];
    const float* ln3_b  = (const float*)d_in[18];
    const float* ff_w1  = (const float*)d_in[19];
    const float* ff_b1  = (const float*)d_in[20];
    const float* ff_w2  = (const float*)d_in[21];
    const float* ff_b2  = (const float*)d_in[22];
    float* out = (float*)d_out;

    const int BF   = in_sizes[0] / (S_Q * D_MODEL);          // 8
    const int ROWS = BF * S_Q;                               // 8192
    const int EB   = in_sizes[1] / (ENC_LEN * ENC_DIM);      // 8
    const int EROWS = EB * ENC_LEN;                          // 616

    static int init_done = 0;
    static cudaStream_t s_side = nullptr;
    static cudaEvent_t evRoot = nullptr, evPack = nullptr, evKV = nullptr;
    if (!init_done) {
        cudaFuncSetAttribute(attn_mma_kernel, cudaFuncAttributeMaxDynamicSharedMemorySize, ATTN_SMEM_BYTES);
        cudaStreamCreateWithFlags(&s_side, cudaStreamNonBlocking);
        cudaEventCreateWithFlags(&evRoot, cudaEventDisableTiming);
        cudaEventCreateWithFlags(&evPack, cudaEventDisableTiming);
        cudaEventCreateWithFlags(&evKV,   cudaEventDisableTiming);
        init_done = 1;
    }

    __half *xh, *abh, *gatedh, *ench, *wqkvh, *o1h, *q2h, *o2h, *wkvh, *w1ph, *w2h;
    float *qkv, *q2b, *kvb, *h2, *h3, *b1p;
    cudaGetSymbolAddress((void**)&xh,     g_xh);
    cudaGetSymbolAddress((void**)&abh,    g_abh);
    cudaGetSymbolAddress((void**)&gatedh, g_gatedh);
    cudaGetSymbolAddress((void**)&ench,   g_ench);
    cudaGetSymbolAddress((void**)&wqkvh,  g_wqkvh);
    cudaGetSymbolAddress((void**)&o1h,    g_o1h);
    cudaGetSymbolAddress((void**)&q2h,    g_q2h);
    cudaGetSymbolAddress((void**)&o2h,    g_o2h);
    cudaGetSymbolAddress((void**)&wkvh,   g_wkvh);
    cudaGetSymbolAddress((void**)&w1ph,   g_w1ph);
    cudaGetSymbolAddress((void**)&w2h,    g_w2h);
    cudaGetSymbolAddress((void**)&qkv,    g_qkv);
    cudaGetSymbolAddress((void**)&q2b,    g_q2);
    cudaGetSymbolAddress((void**)&kvb,    g_kv);
    cudaGetSymbolAddress((void**)&h2,     g_h2);
    cudaGetSymbolAddress((void**)&h3,     g_h3);
    cudaGetSymbolAddress((void**)&b1p,    g_b1p);

    // ---- fork: side stream packs all weights + kv2 GEMM ----
    cudaEventRecord(evRoot, 0);
    cudaStreamWaitEvent(s_side, evRoot, 0);
    {
        run_tcvt(s_side, q1, wqkvh + 0 * D_MODEL * D_MODEL, D_MODEL, D_MODEL);
        run_tcvt(s_side, k1, wqkvh + 1 * D_MODEL * D_MODEL, D_MODEL, D_MODEL);
        run_tcvt(s_side, v1, wqkvh + 2 * D_MODEL * D_MODEL, D_MODEL, D_MODEL);
        run_tcvt(s_side, o1_w, o1h, D_MODEL, D_MODEL);
        run_tcvt(s_side, q2,   q2h, D_MODEL, D_MODEL);
        run_tcvt(s_side, o2_w, o2h, D_MODEL, D_MODEL);
        run_tcvt(s_side, k2, wkvh + 0 * D_MODEL * ENC_DIM, ENC_DIM, D_MODEL);
        run_tcvt(s_side, v2, wkvh + 1 * D_MODEL * ENC_DIM, ENC_DIM, D_MODEL);
        run_tcvt(s_side, ff_w2, w2h, FF_IN, D_MODEL);
        const int nw1 = PROJ_N * D_MODEL;
        w1t_kernel<<<(nw1 + 255) / 256, 256, 0, s_side>>>(ff_w1, w1ph, ff_b1, b1p);
        const int ne = EROWS * ENC_DIM;
        cvt_kernel<<<(ne + 255) / 256, 256, 0, s_side>>>(enc, ench, ne);
    }
    cudaEventRecord(evPack, s_side);
    run_gemm_s(s_side, ench, wkvh, nullptr, nullptr, kvb, EROWS, 2 * D_MODEL, ENC_DIM);
    cudaEventRecord(evKV, s_side);

    // ---- block 1: self-attn with temporal KV gather ----
    run_ln(hidden, ln1_w, ln1_b, xh, ROWS);
    cudaStreamWaitEvent(0, evPack, 0);
    run_gemm(xh, wqkvh, nullptr, nullptr, qkv, ROWS, 3 * D_MODEL, D_MODEL);
    {
        dim3 grid(S_Q / 64, N_HEADS, BF);
        attn_mma_kernel<<<grid, 128, ATTN_SMEM_BYTES>>>(
            qkv, qkv + D_MODEL, qkv + 2 * D_MODEL, abh, vl,
            2 * S_Q, 0, S_Q, 3 * D_MODEL, 3 * D_MODEL);
    }
    run_gemm(abh, o1h, o1_b, hidden, h2, ROWS, D_MODEL, D_MODEL);

    // ---- block 2: cross attention ----
    run_ln(h2, ln2_w, ln2_b, xh, ROWS);
    run_gemm(xh, q2h, nullptr, nullptr, q2b, ROWS, D_MODEL, D_MODEL);
    cudaStreamWaitEvent(0, evKV, 0);
    {
        dim3 grid(S_Q / 64, N_HEADS, BF);
        attn_mma_kernel<<<grid, 128, ATTN_SMEM_BYTES>>>(
            q2b, kvb, kvb + D_MODEL, abh, vl,
            ENC_LEN, 1, ENC_LEN, D_MODEL, 2 * D_MODEL);
    }
    run_gemm(abh, o2h, o2_b, h2, h3, ROWS, D_MODEL, D_MODEL);

    // ---- block 3: fused gated-GeLU FF ----
    run_ln(h3, ln3_w, ln3_b, xh, ROWS);
    run_gemm_gelu(xh, w1ph, b1p, gatedh, ROWS, PROJ_N, D_MODEL);
    run_gemm(gatedh, w2h, ff_b2, h3, out, ROWS, D_MODEL, FF_IN);
}

// round 17
// speedup vs baseline: 1.7467x; 1.2480x over previous
#include <cuda_runtime.h>
#include <cuda_bf16.h>
#include <cuda_fp16.h>
#include <math.h>
#include <stdint.h>

// ---------------- problem constants ----------------
#define S_Q      1024
#define D_MODEL  640
#define N_HEADS  8
#define HD       80
#define ENC_LEN  77
#define ENC_DIM  768
#define FF_IN    2560
#define PROJ_N   5120
#define BF_MAX   8
#define ROWS_MAX (BF_MAX * S_Q)
#define ATTN_SCALE 0.11180339887498949f
#define NEG_BIG  -3.0e38f

// ---------------- scratch ----------------
__device__ __half g_xh[ROWS_MAX * D_MODEL];
__device__ __half g_abh[ROWS_MAX * D_MODEL];
__device__ __half g_gatedh[ROWS_MAX * FF_IN];
__device__ __half g_ench[1024 * ENC_DIM];
__device__ __half g_qkvh[ROWS_MAX * 3 * D_MODEL];
__device__ __half g_q2bh[ROWS_MAX * D_MODEL];
__device__ __half g_kvh[1024 * 2 * D_MODEL];
__device__ float  g_h2[ROWS_MAX * D_MODEL];
__device__ float  g_h3[ROWS_MAX * D_MODEL];
__device__ __half g_wqkvh[3 * D_MODEL * D_MODEL];
__device__ __half g_o1h[D_MODEL * D_MODEL];
__device__ __half g_q2h[D_MODEL * D_MODEL];
__device__ __half g_o2h[D_MODEL * D_MODEL];
__device__ __half g_wkvh[2 * D_MODEL * ENC_DIM];
__device__ __half g_w1ph[PROJ_N * D_MODEL];
__device__ __half g_w2h[D_MODEL * FF_IN];
__device__ float  g_b1p[PROJ_N];

// ---------------- helpers ----------------
__device__ __forceinline__ void mma_f16(float c[4], const uint32_t a[4], const uint32_t b[2]) {
    asm volatile(
        "mma.sync.aligned.m16n8k16.row.col.f32.f16.f16.f32 "
        "{%0,%1,%2,%3}, {%4,%5,%6,%7}, {%8,%9}, {%0,%1,%2,%3};"
        : "+f"(c[0]), "+f"(c[1]), "+f"(c[2]), "+f"(c[3])
        : "r"(a[0]), "r"(a[1]), "r"(a[2]), "r"(a[3]), "r"(b[0]), "r"(b[1]));
}
__device__ __forceinline__ void cp16(void* smem, const void* gmem) {
    uint32_t a = (uint32_t)__cvta_generic_to_shared(smem);
    asm volatile("cp.async.cg.shared.global [%0], [%1], 16;" :: "r"(a), "l"(gmem));
}
#define CP_COMMIT() asm volatile("cp.async.commit_group;")
#define CP_WAIT2()  asm volatile("cp.async.wait_group 2;")

__device__ __forceinline__ float gelu_tanh(float g) {
    const float u = 0.7978845608028654f * (g + 0.044715f * g * g * g);
    return g * __frcp_rn(1.0f + __expf(-2.0f * u));
}

// ---------------- weight packing ----------------
__global__ void tcvt_kernel(const float* __restrict__ src, __half* __restrict__ dst,
                            int K, int N) {
    const int idx = blockIdx.x * blockDim.x + threadIdx.x;
    if (idx >= N * K) return;
    const int n = idx / K, k = idx - n * K;
    dst[idx] = __float2half(src[(size_t)k * N + n]);
}
__global__ void w1t_kernel(const float* __restrict__ w, __half* __restrict__ dst,
                           const float* __restrict__ b, float* __restrict__ bout) {
    const int idx = blockIdx.x * blockDim.x + threadIdx.x;
    if (idx < PROJ_N) {
        const int jb = idx >> 1, sb = idx & 1;
        bout[idx] = b[sb * FF_IN + jb];
    }
    if (idx >= PROJ_N * D_MODEL) return;
    const int n = idx / D_MODEL, k = idx - n * D_MODEL;
    const int j = n >> 1, s = n & 1;
    dst[idx] = __float2half(w[(size_t)k * PROJ_N + s * FF_IN + j]);
}
__global__ void cvt_kernel(const float* __restrict__ src, __half* __restrict__ dst, int n) {
    const int idx = blockIdx.x * blockDim.x + threadIdx.x;
    if (idx < n) dst[idx] = __float2half(src[idx]);
}

// ---------------- LayerNorm: warp-per-row, half output ----------------
__global__ __launch_bounds__(256) void ln_kernel(
    const float* __restrict__ x, const float* __restrict__ w,
    const float* __restrict__ b, __half* __restrict__ out, int rows) {
    const int warp = threadIdx.x >> 5, lane = threadIdx.x & 31;
    const int row = blockIdx.x * 8 + warp;
    if (row >= rows) return;
    const float* xr = x + (size_t)row * D_MODEL;
    __half* orow = out + (size_t)row * D_MODEL;

    float4 v[5];
    float s = 0.f, s2 = 0.f;
    #pragma unroll
    for (int i = 0; i < 5; i++) {
        v[i] = *(const float4*)(xr + i * 128 + lane * 4);
        s  += v[i].x + v[i].y + v[i].z + v[i].w;
        s2 += v[i].x * v[i].x + v[i].y * v[i].y + v[i].z * v[i].z + v[i].w * v[i].w;
    }
    #pragma unroll
    for (int o = 16; o; o >>= 1) {
        s  += __shfl_xor_sync(0xFFFFFFFFu, s,  o);
        s2 += __shfl_xor_sync(0xFFFFFFFFu, s2, o);
    }
    const float mean = s * (1.0f / D_MODEL);
    const float var  = s2 * (1.0f / D_MODEL) - mean * mean;
    const float rstd = rsqrtf(var + 1e-5f);
    #pragma unroll
    for (int i = 0; i < 5; i++) {
        const int c = i * 128 + lane * 4;
        const float4 wv = *(const float4*)(w + c);
        const float4 bv = *(const float4*)(b + c);
        *(half2*)(orow + c)     = __floats2half2_rn((v[i].x - mean) * rstd * wv.x + bv.x,
                                                    (v[i].y - mean) * rstd * wv.y + bv.y);
        *(half2*)(orow + c + 2) = __floats2half2_rn((v[i].z - mean) * rstd * wv.z + bv.z,
                                                    (v[i].w - mean) * rstd * wv.w + bv.w);
    }
}

// ---------------- fp16 GEMM: 128x128, 8 warps, warp 32x64, BK16, 4-stage ----------------
// OUT: 0 = fp32 C (+bias/resid), 1 = gated-gelu half, 2 = plain half C
#define AHALF 24
#define GSTAGES 4

template<int OUT>
__global__ __launch_bounds__(256, 2) void gemm_f16_kernel_t(
    const __half* __restrict__ A, const __half* __restrict__ B,
    const float* __restrict__ bias, const float* __restrict__ resid,
    float* __restrict__ C, __half* __restrict__ Ch, int M, int N, int K)
{
    __shared__ __half As[GSTAGES][128 * AHALF];
    __shared__ __half Bs[GSTAGES][128 * AHALF];

    const int tid  = threadIdx.x;
    const int lane = tid & 31, warp = tid >> 5;
    const int wm = warp & 3, wn = warp >> 2;
    const int g  = lane >> 2, tg = lane & 3;
    const int bm = blockIdx.y * 128, bn = blockIdx.x * 128;

    const int prow = tid >> 1;
    const int pk   = (tid & 1) * 8;
    const __half* Ap = A + (size_t)min(bm + prow, M - 1) * K + pk;
    const __half* Bp = B + (size_t)(bn + prow) * K + pk;

    float acc[2][8][4];
    #pragma unroll
    for (int mt = 0; mt < 2; mt++)
        #pragma unroll
        for (int nt = 0; nt < 8; nt++)
            #pragma unroll
            for (int i = 0; i < 4; i++) acc[mt][nt][i] = 0.f;

    const int T = K >> 4;

    #pragma unroll
    for (int s = 0; s < GSTAGES - 1; s++) {
        if (s < T) {
            cp16(&As[s][prow * AHALF + pk], Ap + s * 16);
            cp16(&Bs[s][prow * AHALF + pk], Bp + s * 16);
        }
        CP_COMMIT();
    }

    for (int t = 0; t < T; t++) {
        CP_WAIT2();
        __syncthreads();

        const int cur = t & (GSTAGES - 1);
        const __half* as = As[cur];
        const __half* bs = Bs[cur];
        uint32_t af[2][4], bf[8][2];
        #pragma unroll
        for (int mt = 0; mt < 2; mt++) {
            const int r = wm * 32 + mt * 16 + g;
            af[mt][0] = *(const uint32_t*)(as + r * AHALF + 2 * tg);
            af[mt][1] = *(const uint32_t*)(as + (r + 8) * AHALF + 2 * tg);
            af[mt][2] = *(const uint32_t*)(as + r * AHALF + 2 * tg + 8);
            af[mt][3] = *(const uint32_t*)(as + (r + 8) * AHALF + 2 * tg + 8);
        }
        #pragma unroll
        for (int nt = 0; nt < 8; nt++) {
            const int rn = wn * 64 + nt * 8 + g;
            bf[nt][0] = *(const uint32_t*)(bs + rn * AHALF + 2 * tg);
            bf[nt][1] = *(const uint32_t*)(bs + rn * AHALF + 2 * tg + 8);
        }
        #pragma unroll
        for (int mt = 0; mt < 2; mt++)
            #pragma unroll
            for (int nt = 0; nt < 8; nt++)
                mma_f16(acc[mt][nt], af[mt], bf[nt]);

        const int tn = t + GSTAGES - 1;
        if (tn < T) {
            const int nxt = tn & (GSTAGES - 1);
            cp16(&As[nxt][prow * AHALF + pk], Ap + tn * 16);
            cp16(&Bs[nxt][prow * AHALF + pk], Bp + tn * 16);
        }
        CP_COMMIT();
    }

    if (OUT == 1) {
        const int NO = N >> 1;
        #pragma unroll
        for (int nt = 0; nt < 8; nt++) {
            const int c = bn + wn * 64 + nt * 8 + tg * 2;
            const float2 bv = *(const float2*)(bias + c);
            const int j = c >> 1;
            #pragma unroll
            for (int mt = 0; mt < 2; mt++) {
                const int r0 = bm + wm * 32 + mt * 16 + g;
                if (r0 < M)
                    Ch[(size_t)r0 * NO + j] = __float2half((acc[mt][nt][0] + bv.x) * gelu_tanh(acc[mt][nt][1] + bv.y));
                const int r1 = r0 + 8;
                if (r1 < M)
                    Ch[(size_t)r1 * NO + j] = __float2half((acc[mt][nt][2] + bv.x) * gelu_tanh(acc[mt][nt][3] + bv.y));
            }
        }
    } else if (OUT == 2) {
        #pragma unroll
        for (int nt = 0; nt < 8; nt++) {
            const int c = bn + wn * 64 + nt * 8 + tg * 2;
            #pragma unroll
            for (int mt = 0; mt < 2; mt++) {
                const int r0 = bm + wm * 32 + mt * 16 + g;
                if (r0 < M)
                    *(half2*)(Ch + (size_t)r0 * N + c) = __floats2half2_rn(acc[mt][nt][0], acc[mt][nt][1]);
                const int r1 = r0 + 8;
                if (r1 < M)
                    *(half2*)(Ch + (size_t)r1 * N + c) = __floats2half2_rn(acc[mt][nt][2], acc[mt][nt][3]);
            }
        }
    } else {
        #pragma unroll
        for (int nt = 0; nt < 8; nt++) {
            const int c = bn + wn * 64 + nt * 8 + tg * 2;
            float bx = 0.f, by = 0.f;
            if (bias) { const float2 bv = *(const float2*)(bias + c); bx = bv.x; by = bv.y; }
            #pragma unroll
            for (int mt = 0; mt < 2; mt++) {
                const int r0 = bm + wm * 32 + mt * 16 + g;
                if (r0 < M) {
                    float2 v = make_float2(acc[mt][nt][0] + bx, acc[mt][nt][1] + by);
                    if (resid) { const float2 rv = *(const float2*)(resid + (size_t)r0 * N + c); v.x += rv.x; v.y += rv.y; }
                    *(float2*)(C + (size_t)r0 * N + c) = v;
                }
                const int r1 = r0 + 8;
                if (r1 < M) {
                    float2 v = make_float2(acc[mt][nt][2] + bx, acc[mt][nt][3] + by);
                    if (resid) { const float2 rv = *(const float2*)(resid + (size_t)r1 * N + c); v.x += rv.x; v.y += rv.y; }
                    *(float2*)(C + (size_t)r1 * N + c) = v;
                }
            }
        }
    }
}

// ---------------- fp16 MMA flash attention: 64-q tile, 4 warps, half smem ----------------
// Ks [key][d] 88-half rows; Vs [d][key] 72-half rows; Ps [row][key] 72-half rows.
#define KSH 88
#define VSH 72
#define PSH 72
#define KS_OFF 0
#define VS_OFF (64 * KSH)                        // 5632 halves
#define PS_OFF (VS_OFF + 80 * VSH)               // 11392
#define ATTN_SMEM_HALVES (PS_OFF + 64 * PSH)     // 16000
#define ATTN_SMEM_BYTES  (ATTN_SMEM_HALVES * 2)  // 32000

__global__ __launch_bounds__(128, 3) void attn_mma_kernel(
    const __half* __restrict__ Q, const __half* __restrict__ Kbuf,
    const __half* __restrict__ Vbuf, __half* __restrict__ O,
    const int* __restrict__ vlp, int kv_len, int mode, int kv_seq,
    int qld, int kvld)
{
    extern __shared__ __half smh[];
    __half* Ks = smh + KS_OFF;
    __half* Vs = smh + VS_OFF;
    __half* Ps = smh + PS_OFF;

    const int tid  = threadIdx.x;
    const int lane = tid & 31, warp = tid >> 5;
    const int g = lane >> 2, tg = lane & 3;
    const int h  = blockIdx.y;
    const int bf = blockIdx.z;
    const int q0 = blockIdx.x * 64;

    int frame0_row0, prev_row0 = 0;
    if (mode == 0) {
        const int f = vlp[0];
        const int b_idx = bf / f;
        const int fr = bf - b_idx * f;
        const int pf = (fr == 0) ? 0 : (fr - 1);
        frame0_row0 = (b_idx * f) * kv_seq;
        prev_row0   = (b_idx * f + pf) * kv_seq;
    } else {
        frame0_row0 = bf * kv_seq;
    }

    // ---- Q fragments straight from half gmem (5 k16 chunks) ----
    uint32_t qf[5][4];
    {
        const __half* q0p = Q + ((size_t)bf * S_Q + q0 + warp * 16 + g) * qld + h * HD;
        const __half* q1p = q0p + (size_t)8 * qld;
        #pragma unroll
        for (int c = 0; c < 5; c++) {
            qf[c][0] = *(const uint32_t*)(q0p + c * 16 + 2 * tg);
            qf[c][1] = *(const uint32_t*)(q1p + c * 16 + 2 * tg);
            qf[c][2] = *(const uint32_t*)(q0p + c * 16 + 2 * tg + 8);
            qf[c][3] = *(const uint32_t*)(q1p + c * 16 + 2 * tg + 8);
        }
    }

    float o[10][4];
    #pragma unroll
    for (int nt = 0; nt < 10; nt++)
        #pragma unroll
        for (int i = 0; i < 4; i++) o[nt][i] = 0.f;
    float m0 = NEG_BIG, m1 = NEG_BIG, l0 = 0.f, l1 = 0.f;

    // KV producer: 128 threads = (key kj = tid>>1, half-range kq = (tid&1)*40)
    const int kj = tid >> 1;
    const int kq = (tid & 1) * 40;

    const int ntiles = (kv_len + 63) >> 6;
    for (int t = 0; t < ntiles; t++) {
        const int kbase = t * 64;
        {
            const int jg = kbase + kj;
            const bool valid = jg < kv_len;
            int row = 0;
            if (valid) {
                if (mode == 0) row = (jg < kv_seq) ? (frame0_row0 + jg) : (prev_row0 + jg - kv_seq);
                else           row = frame0_row0 + jg;
            }
            const __half* ksrc = Kbuf + (size_t)row * kvld + h * HD + kq;
            const __half* vsrc = Vbuf + (size_t)row * kvld + h * HD + kq;
            // K native copy: 5 x uint4 (8 halves each)
            __half* kdst = Ks + kj * KSH + kq;
            #pragma unroll
            for (int i = 0; i < 5; i++) {
                uint4 kv = valid ? *(const uint4*)(ksrc + i * 8) : make_uint4(0,0,0,0);
                *(uint4*)(kdst + i * 8) = kv;
            }
            // V transposed scatter
            #pragma unroll
            for (int i = 0; i < 5; i++) {
                uint4 vv = valid ? *(const uint4*)(vsrc + i * 8) : make_uint4(0,0,0,0);
                const __half* vh = (const __half*)&vv;
                const int d = kq + i * 8;
                #pragma unroll
                for (int j = 0; j < 8; j++)
                    Vs[(d + j) * VSH + kj] = vh[j];
            }
        }
        __syncthreads();

        // ---- S = Q @ K^T (5 k16 chunks x 8 nt) ----
        float s[8][4];
        #pragma unroll
        for (int nt = 0; nt < 8; nt++)
            #pragma unroll
            for (int i = 0; i < 4; i++) s[nt][i] = 0.f;

        #pragma unroll
        for (int c = 0; c < 5; c++) {
            uint32_t bfg[8][2];
            #pragma unroll
            for (int nt = 0; nt < 8; nt++) {
                const __half* bp = Ks + (nt * 8 + g) * KSH + c * 16 + 2 * tg;
                bfg[nt][0] = *(const uint32_t*)(bp);
                bfg[nt][1] = *(const uint32_t*)(bp + 8);
            }
            #pragma unroll
            for (int nt = 0; nt < 8; nt++) mma_f16(s[nt], qf[c], bfg[nt]);
        }

        // ---- scale + mask + online softmax ----
        float mx0 = NEG_BIG, mx1 = NEG_BIG;
        #pragma unroll
        for (int nt = 0; nt < 8; nt++) {
            s[nt][0] *= ATTN_SCALE; s[nt][1] *= ATTN_SCALE;
            s[nt][2] *= ATTN_SCALE; s[nt][3] *= ATTN_SCALE;
            if (mode == 1) {
                const int c0 = kbase + nt * 8 + 2 * tg;
                if (c0 >= kv_len)     { s[nt][0] = NEG_BIG; s[nt][2] = NEG_BIG; }
                if (c0 + 1 >= kv_len) { s[nt][1] = NEG_BIG; s[nt][3] = NEG_BIG; }
            }
            mx0 = fmaxf(mx0, fmaxf(s[nt][0], s[nt][1]));
            mx1 = fmaxf(mx1, fmaxf(s[nt][2], s[nt][3]));
        }
        mx0 = fmaxf(mx0, __shfl_xor_sync(0xFFFFFFFFu, mx0, 1));
        mx0 = fmaxf(mx0, __shfl_xor_sync(0xFFFFFFFFu, mx0, 2));
        mx1 = fmaxf(mx1, __shfl_xor_sync(0xFFFFFFFFu, mx1, 1));
        mx1 = fmaxf(mx1, __shfl_xor_sync(0xFFFFFFFFu, mx1, 2));

        const float mn0 = fmaxf(m0, mx0), mn1 = fmaxf(m1, mx1);
        const float a0 = __expf(m0 - mn0), a1 = __expf(m1 - mn1);
        l0 *= a0; l1 *= a1;
        #pragma unroll
        for (int nt = 0; nt < 10; nt++) {
            o[nt][0] *= a0; o[nt][1] *= a0; o[nt][2] *= a1; o[nt][3] *= a1;
        }

        float ls0 = 0.f, ls1 = 0.f;
        {
            __half* pr0 = Ps + (warp * 16 + g) * PSH + 2 * tg;
            __half* pr1 = pr0 + 8 * PSH;
            #pragma unroll
            for (int nt = 0; nt < 8; nt++) {
                const float p0 = __expf(s[nt][0] - mn0);
                const float p1 = __expf(s[nt][1] - mn0);
                const float p2 = __expf(s[nt][2] - mn1);
                const float p3 = __expf(s[nt][3] - mn1);
                ls0 += p0 + p1; ls1 += p2 + p3;
                *(half2*)(pr0 + nt * 8) = __floats2half2_rn(p0, p1);
                *(half2*)(pr1 + nt * 8) = __floats2half2_rn(p2, p3);
            }
        }
        ls0 += __shfl_xor_sync(0xFFFFFFFFu, ls0, 1);
        ls0 += __shfl_xor_sync(0xFFFFFFFFu, ls0, 2);
        ls1 += __shfl_xor_sync(0xFFFFFFFFu, ls1, 1);
        ls1 += __shfl_xor_sync(0xFFFFFFFFu, ls1, 2);
        l0 += ls0; l1 += ls1;
        m0 = mn0; m1 = mn1;
        __syncwarp();

        // ---- O += P @ V (4 k16 chunks x 10 nt) ----
        #pragma unroll
        for (int c = 0; c < 4; c++) {
            uint32_t af[4], bfg[10][2];
            const __half* ap = Ps + (warp * 16 + g) * PSH + c * 16 + 2 * tg;
            af[0] = *(const uint32_t*)(ap);
            af[1] = *(const uint32_t*)(ap + 8 * PSH);
            af[2] = *(const uint32_t*)(ap + 8);
            af[3] = *(const uint32_t*)(ap + 8 * PSH + 8);
            #pragma unroll
            for (int nt = 0; nt < 10; nt++) {
                const __half* bp = Vs + (nt * 8 + g) * VSH + c * 16 + 2 * tg;
                bfg[nt][0] = *(const uint32_t*)(bp);
                bfg[nt][1] = *(const uint32_t*)(bp + 8);
            }
            #pragma unroll
            for (int nt = 0; nt < 10; nt++) mma_f16(o[nt], af, bfg[nt]);
        }
        __syncthreads();
    }

    const float inv0 = 1.0f / l0, inv1 = 1.0f / l1;
    const size_t r0 = (size_t)bf * S_Q + q0 + warp * 16 + g;
    const size_t r1 = r0 + 8;
    __half* o0 = O + r0 * D_MODEL + h * HD + 2 * tg;
    __half* o1 = O + r1 * D_MODEL + h * HD + 2 * tg;
    #pragma unroll
    for (int nt = 0; nt < 10; nt++) {
        *(half2*)(o0 + nt * 8) = __floats2half2_rn(o[nt][0] * inv0, o[nt][1] * inv0);
        *(half2*)(o1 + nt * 8) = __floats2half2_rn(o[nt][2] * inv1, o[nt][3] * inv1);
    }
}

// ---------------- host ----------------
static inline void run_gemm_s(cudaStream_t st, const __half* A, const __half* B,
                              const float* bias, const float* resid, float* C,
                              int M, int N, int K) {
    dim3 grid(N / 128, (M + 127) / 128);
    gemm_f16_kernel_t<0><<<grid, 256, 0, st>>>(A, B, bias, resid, C, nullptr, M, N, K);
}
static inline void run_gemm(const __half* A, const __half* B, const float* bias,
                            const float* resid, float* C, int M, int N, int K) {
    run_gemm_s(0, A, B, bias, resid, C, M, N, K);
}
static inline void run_gemm_h(cudaStream_t st, const __half* A, const __half* B,
                              __half* Ch, int M, int N, int K) {
    dim3 grid(N / 128, (M + 127) / 128);
    gemm_f16_kernel_t<2><<<grid, 256, 0, st>>>(A, B, nullptr, nullptr, nullptr, Ch, M, N, K);
}
static inline void run_gemm_gelu(const __half* A, const __half* B, const float* bias,
                                 __half* Ch, int M, int N, int K) {
    dim3 grid(N / 128, (M + 127) / 128);
    gemm_f16_kernel_t<1><<<grid, 256>>>(A, B, bias, nullptr, nullptr, Ch, M, N, K);
}
static inline void run_ln(const float* x, const float* w, const float* b,
                          __half* out, int rows) {
    ln_kernel<<<(rows + 7) / 8, 256>>>(x, w, b, out, rows);
}
static inline void run_tcvt(cudaStream_t st, const float* src, __half* dst, int K, int N) {
    const int n = N * K;
    tcvt_kernel<<<(n + 255) / 256, 256, 0, st>>>(src, dst, K, N);
}

extern "C" void kernel_launch(void* const* d_in, const int* in_sizes, int n_in,
                              void* d_out, int out_size) {
    const float* hidden = (const float*)d_in[0];
    const float* enc    = (const float*)d_in[1];
    const int*   vl     = (const int*)d_in[2];
    const float* ln1_w  = (const float*)d_in[3];
    const float* ln1_b  = (const float*)d_in[4];
    const float* q1     = (const float*)d_in[5];
    const float* k1     = (const float*)d_in[6];
    const float* v1     = (const float*)d_in[7];
    const float* o1_w   = (const float*)d_in[8];
    const float* o1_b   = (const float*)d_in[9];
    const float* ln2_w  = (const float*)d_in[10];
    const float* ln2_b  = (const float*)d_in[11];
    const float* q2     = (const float*)d_in[12];
    const float* k2     = (const float*)d_in[13];
    const float* v2     = (const float*)d_in[14];
    const float* o2_w   = (const float*)d_in[15];
    const float* o2_b   = (const float*)d_in[16];
    const float* ln3_w  = (const float*)d_in[17];
    const float* ln3_b  = (const float*)d_in[18];
    const float* ff_w1  = (const float*)d_in[19];
    const float* ff_b1  = (const float*)d_in[20];
    const float* ff_w2  = (const float*)d_in[21];
    const float* ff_b2  = (const float*)d_in[22];
    float* out = (float*)d_out;

    const int BF   = in_sizes[0] / (S_Q * D_MODEL);          // 8
    const int ROWS = BF * S_Q;                               // 8192
    const int EB   = in_sizes[1] / (ENC_LEN * ENC_DIM);      // 8
    const int EROWS = EB * ENC_LEN;                          // 616

    static int init_done = 0;
    static cudaStream_t s_side = nullptr;
    static cudaEvent_t evRoot = nullptr, evPack = nullptr, evKV = nullptr;
    if (!init_done) {
        cudaFuncSetAttribute(attn_mma_kernel, cudaFuncAttributeMaxDynamicSharedMemorySize, ATTN_SMEM_BYTES);
        cudaStreamCreateWithFlags(&s_side, cudaStreamNonBlocking);
        cudaEventCreateWithFlags(&evRoot, cudaEventDisableTiming);
        cudaEventCreateWithFlags(&evPack, cudaEventDisableTiming);
        cudaEventCreateWithFlags(&evKV,   cudaEventDisableTiming);
        init_done = 1;
    }

    __half *xh, *abh, *gatedh, *ench, *qkvh, *q2bh, *kvh;
    __half *wqkvh, *o1h, *q2h, *o2h, *wkvh, *w1ph, *w2h;
    float *h2, *h3, *b1p;
    cudaGetSymbolAddress((void**)&xh,     g_xh);
    cudaGetSymbolAddress((void**)&abh,    g_abh);
    cudaGetSymbolAddress((void**)&gatedh, g_gatedh);
    cudaGetSymbolAddress((void**)&ench,   g_ench);
    cudaGetSymbolAddress((void**)&qkvh,   g_qkvh);
    cudaGetSymbolAddress((void**)&q2bh,   g_q2bh);
    cudaGetSymbolAddress((void**)&kvh,    g_kvh);
    cudaGetSymbolAddress((void**)&wqkvh,  g_wqkvh);
    cudaGetSymbolAddress((void**)&o1h,    g_o1h);
    cudaGetSymbolAddress((void**)&q2h,    g_q2h);
    cudaGetSymbolAddress((void**)&o2h,    g_o2h);
    cudaGetSymbolAddress((void**)&wkvh,   g_wkvh);
    cudaGetSymbolAddress((void**)&w1ph,   g_w1ph);
    cudaGetSymbolAddress((void**)&w2h,    g_w2h);
    cudaGetSymbolAddress((void**)&h2,     g_h2);
    cudaGetSymbolAddress((void**)&h3,     g_h3);
    cudaGetSymbolAddress((void**)&b1p,    g_b1p);

    // ---- fork: side stream packs weights + kv2 GEMM ----
    cudaEventRecord(evRoot, 0);
    cudaStreamWaitEvent(s_side, evRoot, 0);
    {
        run_tcvt(s_side, q1, wqkvh + 0 * D_MODEL * D_MODEL, D_MODEL, D_MODEL);
        run_tcvt(s_side, k1, wqkvh + 1 * D_MODEL * D_MODEL, D_MODEL, D_MODEL);
        run_tcvt(s_side, v1, wqkvh + 2 * D_MODEL * D_MODEL, D_MODEL, D_MODEL);
        run_tcvt(s_side, o1_w, o1h, D_MODEL, D_MODEL);
        run_tcvt(s_side, q2,   q2h, D_MODEL, D_MODEL);
        run_tcvt(s_side, o2_w, o2h, D_MODEL, D_MODEL);
        run_tcvt(s_side, k2, wkvh + 0 * D_MODEL * ENC_DIM, ENC_DIM, D_MODEL);
        run_tcvt(s_side, v2, wkvh + 1 * D_MODEL * ENC_DIM, ENC_DIM, D_MODEL);
        run_tcvt(s_side, ff_w2, w2h, FF_IN, D_MODEL);
        const int nw1 = PROJ_N * D_MODEL;
        w1t_kernel<<<(nw1 + 255) / 256, 256, 0, s_side>>>(ff_w1, w1ph, ff_b1, b1p);
        const int ne = EROWS * ENC_DIM;
        cvt_kernel<<<(ne + 255) / 256, 256, 0, s_side>>>(enc, ench, ne);
    }
    cudaEventRecord(evPack, s_side);
    run_gemm_h(s_side, ench, wkvh, kvh, EROWS, 2 * D_MODEL, ENC_DIM);
    cudaEventRecord(evKV, s_side);

    // ---- block 1: self-attn with temporal KV gather ----
    run_ln(hidden, ln1_w, ln1_b, xh, ROWS);
    cudaStreamWaitEvent(0, evPack, 0);
    run_gemm_h(0, xh, wqkvh, qkvh, ROWS, 3 * D_MODEL, D_MODEL);
    {
        dim3 grid(S_Q / 64, N_HEADS, BF);
        attn_mma_kernel<<<grid, 128, ATTN_SMEM_BYTES>>>(
            qkvh, qkvh + D_MODEL, qkvh + 2 * D_MODEL, abh, vl,
            2 * S_Q, 0, S_Q, 3 * D_MODEL, 3 * D_MODEL);
    }
    run_gemm(abh, o1h, o1_b, hidden, h2, ROWS, D_MODEL, D_MODEL);

    // ---- block 2: cross attention ----
    run_ln(h2, ln2_w, ln2_b, xh, ROWS);
    run_gemm_h(0, xh, q2h, q2bh, ROWS, D_MODEL, D_MODEL);
    cudaStreamWaitEvent(0, evKV, 0);
    {
        dim3 grid(S_Q / 64, N_HEADS, BF);
        attn_mma_kernel<<<grid, 128, ATTN_SMEM_BYTES>>>(
            q2bh, kvh, kvh + D_MODEL, abh, vl,
            ENC_LEN, 1, ENC_LEN, D_MODEL, 2 * D_MODEL);
    }
    run_gemm(abh, o2h, o2_b, h2, h3, ROWS, D_MODEL, D_MODEL);

    // ---- block 3: fused gated-GeLU FF ----
    run_ln(h3, ln3_w, ln3_b, xh, ROWS);
    run_gemm_gelu(xh, w1ph, b1p, gatedh, ROWS, PROJ_N, D_MODEL);
    run_gemm(gatedh, w2h, ff_b2, h3, out, ROWS, D_MODEL, FF_IN);
}